// round 12
// baseline (speedup 1.0000x reference)
#include <cuda_runtime.h>
#include <cuda_bf16.h>
#include <math.h>

#define Nn   100000
#define Ee   1600000
#define ETOT (Ee + Nn)
#define DINq 16
#define Hq   128
#define HEADSq 4
#define Gq   64
#define FOUTq 256
#define NTILE ((Nn + 255) / 256)
#define AUP  132

typedef unsigned long long u64;
typedef unsigned int u32;

// ---- scratch (static device memory) ----
__device__ float g_h[(size_t)Nn * Hq];
__device__ u32   g_hpb[(size_t)Nn * (Hq / 2)];
__device__ float g_alS[Nn * HEADSq];
__device__ float g_alD[Nn * HEADSq];
__device__ int   g_cnt_i[Nn];
__device__ int   g_rowptr[Nn + 1];
__device__ int   g_cursor[Nn];
__device__ int   g_csr_src[ETOT];
__device__ u64   g_tstat[NTILE];
__device__ float g_psum[Gq * Hq];
__device__ float g_pmax[Gq * Hq];
__device__ float g_gcnt[Gq];

#define FLAG_AGG (1ull << 62)
#define FLAG_INC (1ull << 63)

__device__ __forceinline__ void atomicMaxFloat(float* addr, float v) {
    if (v >= 0.0f) atomicMax((int*)addr, __float_as_int(v));
    else           atomicMin((unsigned int*)addr, __float_as_uint(v));
}

__device__ __forceinline__ float gelu_exact(float v) {
    return 0.5f * v * (1.0f + erff(v * 0.70710678118654752f));
}

__device__ __forceinline__ u32 bfpack(float lo, float hi) {
    u32 r; asm("cvt.rn.bf16x2.f32 %0, %1, %2;" : "=r"(r) : "f"(hi), "f"(lo)); return r;
}

__device__ __forceinline__ u32 tf32cvt(float f) {
    u32 r; asm("cvt.rna.tf32.f32 %0, %1;" : "=r"(r) : "f"(f)); return r;
}

__device__ __forceinline__ void mma_tf32(float* c, const u32* a, u32 b0, u32 b1) {
    asm volatile("mma.sync.aligned.m16n8k8.row.col.f32.tf32.tf32.f32 "
        "{%0,%1,%2,%3}, {%4,%5,%6,%7}, {%8,%9}, {%0,%1,%2,%3};"
        : "+f"(c[0]), "+f"(c[1]), "+f"(c[2]), "+f"(c[3])
        : "r"(a[0]), "r"(a[1]), "r"(a[2]), "r"(a[3]), "r"(b0), "r"(b1));
}

__device__ __forceinline__ float bflo(u32 w) { return __uint_as_float(w << 16); }
__device__ __forceinline__ float bfhi(u32 w) { return __uint_as_float(w & 0xffff0000u); }

// ======= FUSED: proj(FFMA) + layer0 GEMM(tf32) + edge histogram side-job =======
// dynamic smem: Au[128][AUP] u32  +  tail max( xs[128][17]+wps[16][132] , Wu[32][136] )
__global__ void __launch_bounds__(256) gemm_fused0(
    const float* __restrict__ x, const float* __restrict__ Wp, const float* __restrict__ bp,
    const float* __restrict__ W, const float* __restrict__ a_s, const float* __restrict__ a_d,
    const int* __restrict__ ei, int M)
{
    extern __shared__ u32 dyn[];
    u32 (*Au)[AUP] = (u32(*)[AUP])dyn;
    u32* tail = dyn + 128 * AUP;
    float* xs  = (float*)tail;          // [128][17]
    float* wps = xs + 128 * 17;         // [16][132]
    u32 (*Wu)[136] = (u32(*)[136])tail; // phase-2 alias

    int tid = threadIdx.x;
    int m0 = blockIdx.x * 128;

    // side job A: zero lookback status
    int gt0 = blockIdx.x * 256 + tid;
    if (gt0 < NTILE) g_tstat[gt0] = 0;

    // ---- phase 1: load x tile + Wp ----
    for (int i = tid; i < 128 * 16; i += 256) {
        int r = i >> 4, k = i & 15;
        int m = m0 + r;
        xs[r * 17 + k] = (m < M) ? x[(size_t)m * DINq + k] : 0.f;
    }
    for (int i = tid; i < 16 * 128; i += 256) {
        int k = i >> 7, c = i & 127;
        wps[k * 132 + c] = Wp[k * Hq + c];
    }
    __syncthreads();

    int tx = tid & 15, ty = tid >> 4;
    int c0 = tx * 8, r0 = ty * 8;
    float b8[8];
#pragma unroll
    for (int q = 0; q < 8; q++) b8[q] = bp[c0 + q];

#pragma unroll
    for (int rh = 0; rh < 2; rh++) {
        float v[4][8];
#pragma unroll
        for (int rr = 0; rr < 4; rr++)
#pragma unroll
            for (int q = 0; q < 8; q++) v[rr][q] = 0.f;
#pragma unroll
        for (int k = 0; k < 16; k++) {
            float w8[8];
#pragma unroll
            for (int q = 0; q < 8; q++) w8[q] = wps[k * 132 + c0 + q];
#pragma unroll
            for (int rr = 0; rr < 4; rr++) {
                float a = xs[(r0 + rh * 4 + rr) * 17 + k];
#pragma unroll
                for (int q = 0; q < 8; q++) v[rr][q] += a * w8[q];
            }
        }
#pragma unroll
        for (int rr = 0; rr < 4; rr++) {
            int r = r0 + rh * 4 + rr;
            int m = m0 + r;
#pragma unroll
            for (int q = 0; q < 8; q++) v[rr][q] = gelu_exact(v[rr][q] + b8[q]);
            if (m < M) {
                *(float4*)&g_h[(size_t)m * Hq + c0] =
                    make_float4(v[rr][0], v[rr][1], v[rr][2], v[rr][3]);
                *(float4*)&g_h[(size_t)m * Hq + c0 + 4] =
                    make_float4(v[rr][4], v[rr][5], v[rr][6], v[rr][7]);
            }
#pragma unroll
            for (int q = 0; q < 8; q++) Au[r][c0 + q] = tf32cvt(v[rr][q]);
        }
    }

    // side job B: edge histogram (grid-stride)
    for (int e = blockIdx.x * 256 + tid; e < ETOT; e += gridDim.x * 256) {
        int d = (e < Ee) ? ei[Ee + e] : (e - Ee);
        atomicAdd(&g_cnt_i[d], 1);
    }

    __syncthreads();   // Au ready; phase-1 tail region free

    // ---- phase 2: tf32 tensor-core GEMM, A from smem ----
    int w = tid >> 5, lane = tid & 31;
    int wr = w >> 1, wc = w & 1;
    int q = lane & 3, g = lane >> 2;

    float c[2][8][4];
#pragma unroll
    for (int mt = 0; mt < 2; mt++)
#pragma unroll
        for (int nt = 0; nt < 8; nt++)
#pragma unroll
            for (int f = 0; f < 4; f++) c[mt][nt][f] = 0.f;

    for (int kc = 0; kc < 128; kc += 32) {
#pragma unroll
        for (int it = 0; it < 4; it++) {
            int idx = (it * 256 + tid) * 4;
            int r = idx >> 7, cI = idx & 127;
            float4 v4 = *(const float4*)&W[(size_t)(kc + r) * Hq + cI];
            Wu[r][cI + 0] = tf32cvt(v4.x);
            Wu[r][cI + 1] = tf32cvt(v4.y);
            Wu[r][cI + 2] = tf32cvt(v4.z);
            Wu[r][cI + 3] = tf32cvt(v4.w);
        }
        __syncthreads();
#pragma unroll
        for (int kt = 0; kt < 32; kt += 8) {
            u32 af[2][4];
#pragma unroll
            for (int mt = 0; mt < 2; mt++) {
                int r = wr * 32 + mt * 16;
                af[mt][0] = Au[r + g][kc + kt + q];
                af[mt][1] = Au[r + g + 8][kc + kt + q];
                af[mt][2] = Au[r + g][kc + kt + q + 4];
                af[mt][3] = Au[r + g + 8][kc + kt + q + 4];
            }
#pragma unroll
            for (int nt = 0; nt < 8; nt++) {
                int n = wc * 64 + nt * 8 + g;
                u32 b0 = Wu[kt + q][n];
                u32 b1 = Wu[kt + q + 4][n];
                mma_tf32(c[0][nt], af[0], b0, b1);
                mma_tf32(c[1][nt], af[1], b0, b1);
            }
        }
        __syncthreads();
    }

    // epilogue 1: bf16 pack
#pragma unroll
    for (int mt = 0; mt < 2; mt++)
#pragma unroll
        for (int half = 0; half < 2; half++) {
            int m = m0 + wr * 32 + mt * 16 + g + half * 8;
            if (m < M) {
#pragma unroll
                for (int nt = 0; nt < 8; nt++) {
                    u32 pw = bfpack(c[mt][nt][2 * half], c[mt][nt][2 * half + 1]);
                    g_hpb[(size_t)m * (Hq / 2) + wc * 32 + nt * 4 + q] = pw;
                }
            }
        }

    // epilogue 2: attn logits
    float asv[8][2], adv[8][2];
#pragma unroll
    for (int nt = 0; nt < 8; nt++) {
        int col = wc * 64 + nt * 8 + 2 * q;
        asv[nt][0] = a_s[col];     asv[nt][1] = a_s[col + 1];
        adv[nt][0] = a_d[col];     adv[nt][1] = a_d[col + 1];
    }
#pragma unroll
    for (int mt = 0; mt < 2; mt++)
#pragma unroll
        for (int half = 0; half < 2; half++) {
            int m = m0 + wr * 32 + mt * 16 + g + half * 8;
            float ps0 = 0.f, ps1 = 0.f, pd0 = 0.f, pd1 = 0.f;
#pragma unroll
            for (int nt = 0; nt < 8; nt++) {
                float x0 = c[mt][nt][2 * half], x1 = c[mt][nt][2 * half + 1];
                float s = x0 * asv[nt][0] + x1 * asv[nt][1];
                float d = x0 * adv[nt][0] + x1 * adv[nt][1];
                if (nt < 4) { ps0 += s; pd0 += d; }
                else        { ps1 += s; pd1 += d; }
            }
            ps0 += __shfl_xor_sync(0xffffffffu, ps0, 1);
            ps1 += __shfl_xor_sync(0xffffffffu, ps1, 1);
            pd0 += __shfl_xor_sync(0xffffffffu, pd0, 1);
            pd1 += __shfl_xor_sync(0xffffffffu, pd1, 1);
            ps0 += __shfl_xor_sync(0xffffffffu, ps0, 2);
            ps1 += __shfl_xor_sync(0xffffffffu, ps1, 2);
            pd0 += __shfl_xor_sync(0xffffffffu, pd0, 2);
            pd1 += __shfl_xor_sync(0xffffffffu, pd1, 2);
            if (q == 0 && m < M) {
                int hb = wc * 2;
                g_alS[m * 4 + hb]     = ps0;
                g_alS[m * 4 + hb + 1] = ps1;
                g_alD[m * 4 + hb]     = pd0;
                g_alD[m * 4 + hb + 1] = pd1;
            }
        }
}

// ------- layer-1 GEMM (A from global), unchanged -------
__global__ void gemm_tf32(const float* __restrict__ A, const float* __restrict__ W,
                          const float* __restrict__ a_s, const float* __restrict__ a_d, int M)
{
    __shared__ u32 Au[128][36];
    __shared__ u32 Wu[32][136];
    int tid = threadIdx.x;
    int w = tid >> 5, lane = tid & 31;
    int wr = w >> 1, wc = w & 1;
    int q = lane & 3, g = lane >> 2;
    int m0 = blockIdx.x * 128;

    float c[2][8][4];
#pragma unroll
    for (int mt = 0; mt < 2; mt++)
#pragma unroll
        for (int nt = 0; nt < 8; nt++)
#pragma unroll
            for (int f = 0; f < 4; f++) c[mt][nt][f] = 0.f;

    for (int kc = 0; kc < 128; kc += 32) {
#pragma unroll
        for (int it = 0; it < 4; it++) {
            int idx = (it * 256 + tid) * 4;
            int r = idx >> 5, cI = idx & 31;
            float4 v4 = make_float4(0.f, 0.f, 0.f, 0.f);
            if (m0 + r < M) v4 = *(const float4*)&A[(size_t)(m0 + r) * Hq + kc + cI];
            Au[r][cI + 0] = tf32cvt(v4.x);
            Au[r][cI + 1] = tf32cvt(v4.y);
            Au[r][cI + 2] = tf32cvt(v4.z);
            Au[r][cI + 3] = tf32cvt(v4.w);
        }
#pragma unroll
        for (int it = 0; it < 4; it++) {
            int idx = (it * 256 + tid) * 4;
            int r = idx >> 7, cI = idx & 127;
            float4 v4 = *(const float4*)&W[(size_t)(kc + r) * Hq + cI];
            Wu[r][cI + 0] = tf32cvt(v4.x);
            Wu[r][cI + 1] = tf32cvt(v4.y);
            Wu[r][cI + 2] = tf32cvt(v4.z);
            Wu[r][cI + 3] = tf32cvt(v4.w);
        }
        __syncthreads();
#pragma unroll
        for (int kt = 0; kt < 32; kt += 8) {
            u32 af[2][4];
#pragma unroll
            for (int mt = 0; mt < 2; mt++) {
                int r = wr * 32 + mt * 16;
                af[mt][0] = Au[r + g][kt + q];
                af[mt][1] = Au[r + g + 8][kt + q];
                af[mt][2] = Au[r + g][kt + q + 4];
                af[mt][3] = Au[r + g + 8][kt + q + 4];
            }
#pragma unroll
            for (int nt = 0; nt < 8; nt++) {
                int n = wc * 64 + nt * 8 + g;
                u32 b0 = Wu[kt + q][n];
                u32 b1 = Wu[kt + q + 4][n];
                mma_tf32(c[0][nt], af[0], b0, b1);
                mma_tf32(c[1][nt], af[1], b0, b1);
            }
        }
        __syncthreads();
    }

#pragma unroll
    for (int mt = 0; mt < 2; mt++)
#pragma unroll
        for (int half = 0; half < 2; half++) {
            int m = m0 + wr * 32 + mt * 16 + g + half * 8;
            if (m < M) {
#pragma unroll
                for (int nt = 0; nt < 8; nt++) {
                    u32 pw = bfpack(c[mt][nt][2 * half], c[mt][nt][2 * half + 1]);
                    g_hpb[(size_t)m * (Hq / 2) + wc * 32 + nt * 4 + q] = pw;
                }
            }
        }

    float asv[8][2], adv[8][2];
#pragma unroll
    for (int nt = 0; nt < 8; nt++) {
        int col = wc * 64 + nt * 8 + 2 * q;
        asv[nt][0] = a_s[col];     asv[nt][1] = a_s[col + 1];
        adv[nt][0] = a_d[col];     adv[nt][1] = a_d[col + 1];
    }
#pragma unroll
    for (int mt = 0; mt < 2; mt++)
#pragma unroll
        for (int half = 0; half < 2; half++) {
            int m = m0 + wr * 32 + mt * 16 + g + half * 8;
            float ps0 = 0.f, ps1 = 0.f, pd0 = 0.f, pd1 = 0.f;
#pragma unroll
            for (int nt = 0; nt < 8; nt++) {
                float x0 = c[mt][nt][2 * half], x1 = c[mt][nt][2 * half + 1];
                float s = x0 * asv[nt][0] + x1 * asv[nt][1];
                float d = x0 * adv[nt][0] + x1 * adv[nt][1];
                if (nt < 4) { ps0 += s; pd0 += d; }
                else        { ps1 += s; pd1 += d; }
            }
            ps0 += __shfl_xor_sync(0xffffffffu, ps0, 1);
            ps1 += __shfl_xor_sync(0xffffffffu, ps1, 1);
            pd0 += __shfl_xor_sync(0xffffffffu, pd0, 1);
            pd1 += __shfl_xor_sync(0xffffffffu, pd1, 1);
            ps0 += __shfl_xor_sync(0xffffffffu, ps0, 2);
            ps1 += __shfl_xor_sync(0xffffffffu, ps1, 2);
            pd0 += __shfl_xor_sync(0xffffffffu, pd0, 2);
            pd1 += __shfl_xor_sync(0xffffffffu, pd1, 2);
            if (q == 0 && m < M) {
                int hb = wc * 2;
                g_alS[m * 4 + hb]     = ps0;
                g_alS[m * 4 + hb + 1] = ps1;
                g_alD[m * 4 + hb]     = pd0;
                g_alD[m * 4 + hb + 1] = pd1;
            }
        }
}

// ================= CSR build (hist fused into gemm_fused0) =================
__global__ void scan_dl()
{
    __shared__ int s[256];
    __shared__ int s_prefix;
    int bid = blockIdx.x, tid = threadIdx.x;
    int i = bid * 256 + tid;
    int v = (i < Nn) ? g_cnt_i[i] : 0;
    s[tid] = v;
    __syncthreads();
#pragma unroll
    for (int o = 1; o < 256; o <<= 1) {
        int t = (tid >= o) ? s[tid - o] : 0;
        __syncthreads();
        s[tid] += t;
        __syncthreads();
    }
    int incl = s[tid];
    int agg  = s[255];

    if (tid == 0) {
        u64 pub = (bid == 0) ? (FLAG_INC | (u64)(u32)agg) : (FLAG_AGG | (u64)(u32)agg);
        atomicExch((unsigned long long*)&g_tstat[bid], pub);
        if (bid == 0) s_prefix = 0;
    }

    if (bid > 0 && tid < 32) {
        int lane = tid;
        u32 running = 0;
        int look = bid - 1;
        while (true) {
            int t = look - lane;
            u64 st;
            if (t >= 0) {
                do { st = *(volatile u64*)&g_tstat[t]; } while (st == 0);
            } else {
                st = FLAG_INC;
            }
            u32 incm = __ballot_sync(0xffffffffu, (st & FLAG_INC) != 0);
            u32 val;
            if (incm) {
                int L = __ffs(incm) - 1;
                val = (lane <= L) ? (u32)st : 0;
            } else {
                val = (u32)st;
            }
#pragma unroll
            for (int o = 16; o; o >>= 1) val += __shfl_xor_sync(0xffffffffu, val, o);
            running += val;
            if (incm) break;
            look -= 32;
        }
        if (lane == 0) {
            atomicExch((unsigned long long*)&g_tstat[bid],
                       FLAG_INC | (u64)(u32)(running + (u32)agg));
            s_prefix = (int)running;
        }
    }
    __syncthreads();

    int pre = s_prefix;
    if (i < Nn) {
        int r = pre + incl - v;
        g_rowptr[i] = r;
        g_cursor[i] = r;
    }
    if (i == 0) g_rowptr[Nn] = ETOT;
}

__global__ void csr_fill(const int* __restrict__ ei)
{
    int e = blockIdx.x * blockDim.x + threadIdx.x;
    if (e < Nn) g_cnt_i[e] = 0;          // re-zero histogram for next replay
    if (e >= ETOT) return;
    int s, d;
    if (e < Ee) { s = ei[e]; d = ei[Ee + e]; } else { s = d = e - Ee; }
    int pos = atomicAdd(&g_cursor[d], 1);
    g_csr_src[pos] = s;
}

// == GAT aggregation: warp per node, half-warp per edge (unchanged from R10) ==
__global__ void gat_agg_ln(const float* __restrict__ bg, const float* __restrict__ ga,
                           const float* __restrict__ be)
{
    int n = blockIdx.x * 8 + (threadIdx.x >> 5);
    if (n >= Nn) return;
    int lane = threadIdx.x & 31;
    int pairlane = lane >> 4;
    int sub = lane & 15;
    int head = sub >> 2;

    int start = g_rowptr[n];
    int end   = g_rowptr[n + 1];
    float adh = g_alD[n * 4 + head];

    float a[8];
#pragma unroll
    for (int k = 0; k < 8; k++) a[k] = 0.f;
    float den = 0.f;

    int i = start;
    for (; i + 4 <= end; i += 4) {
        int sA = g_csr_src[i + pairlane];
        int sB = g_csr_src[i + 2 + pairlane];
        float lA = g_alS[sA * 4 + head] + adh;
        float lB = g_alS[sB * 4 + head] + adh;
        lA = (lA > 0.f) ? lA : 0.2f * lA;
        lB = (lB > 0.f) ? lB : 0.2f * lB;
        float eA = __expf(lA);
        float eB = __expf(lB);
        uint4 pA = *(const uint4*)&g_hpb[(size_t)sA * 64 + sub * 4];
        uint4 pB = *(const uint4*)&g_hpb[(size_t)sB * 64 + sub * 4];
        den += eA + eB;
        a[0] += eA * bflo(pA.x) + eB * bflo(pB.x);
        a[1] += eA * bfhi(pA.x) + eB * bfhi(pB.x);
        a[2] += eA * bflo(pA.y) + eB * bflo(pB.y);
        a[3] += eA * bfhi(pA.y) + eB * bfhi(pB.y);
        a[4] += eA * bflo(pA.z) + eB * bflo(pB.z);
        a[5] += eA * bfhi(pA.z) + eB * bfhi(pB.z);
        a[6] += eA * bflo(pA.w) + eB * bflo(pB.w);
        a[7] += eA * bfhi(pA.w) + eB * bfhi(pB.w);
    }
    for (; i + 2 <= end; i += 2) {
        int sA = g_csr_src[i + pairlane];
        float lA = g_alS[sA * 4 + head] + adh;
        lA = (lA > 0.f) ? lA : 0.2f * lA;
        float eA = __expf(lA);
        uint4 pA = *(const uint4*)&g_hpb[(size_t)sA * 64 + sub * 4];
        den += eA;
        a[0] += eA * bflo(pA.x);
        a[1] += eA * bfhi(pA.x);
        a[2] += eA * bflo(pA.y);
        a[3] += eA * bfhi(pA.y);
        a[4] += eA * bflo(pA.z);
        a[5] += eA * bfhi(pA.z);
        a[6] += eA * bflo(pA.w);
        a[7] += eA * bfhi(pA.w);
    }
    if (i < end) {
        int sA = g_csr_src[i];
        float lA = g_alS[sA * 4 + head] + adh;
        lA = (lA > 0.f) ? lA : 0.2f * lA;
        float eA = (pairlane == 0) ? __expf(lA) : 0.f;
        uint4 pA = *(const uint4*)&g_hpb[(size_t)sA * 64 + sub * 4];
        den += eA;
        a[0] += eA * bflo(pA.x);
        a[1] += eA * bfhi(pA.x);
        a[2] += eA * bflo(pA.y);
        a[3] += eA * bfhi(pA.y);
        a[4] += eA * bflo(pA.z);
        a[5] += eA * bfhi(pA.z);
        a[6] += eA * bflo(pA.w);
        a[7] += eA * bfhi(pA.w);
    }

    den += __shfl_xor_sync(0xffffffffu, den, 16);
#pragma unroll
    for (int k = 0; k < 8; k++) a[k] += __shfl_xor_sync(0xffffffffu, a[k], 16);

    float dinv = 1.0f / (den + 1e-16f);

    int d0 = sub * 8;
    size_t base = (size_t)n * Hq + d0;
    float4 h0 = *(const float4*)&g_h[base];
    float4 h1 = *(const float4*)&g_h[base + 4];
    float4 b0 = *(const float4*)&bg[d0];
    float4 b1 = *(const float4*)&bg[d0 + 4];
    float v[8];
    v[0] = a[0] * dinv + b0.x + h0.x;
    v[1] = a[1] * dinv + b0.y + h0.y;
    v[2] = a[2] * dinv + b0.z + h0.z;
    v[3] = a[3] * dinv + b0.w + h0.w;
    v[4] = a[4] * dinv + b1.x + h1.x;
    v[5] = a[5] * dinv + b1.y + h1.y;
    v[6] = a[6] * dinv + b1.z + h1.z;
    v[7] = a[7] * dinv + b1.w + h1.w;

    float s = 0.f, t = 0.f;
#pragma unroll
    for (int k = 0; k < 8; k++) { s += v[k]; t += v[k] * v[k]; }
#pragma unroll
    for (int o = 8; o; o >>= 1) {
        s += __shfl_xor_sync(0xffffffffu, s, o);
        t += __shfl_xor_sync(0xffffffffu, t, o);
    }
    float mu = s * (1.0f / 128.0f);
    float var = t * (1.0f / 128.0f) - mu * mu;
    float rs = rsqrtf(var + 1e-5f);

    if (pairlane == 0) {
        float4 g0 = *(const float4*)&ga[d0];
        float4 g1 = *(const float4*)&ga[d0 + 4];
        float4 e0 = *(const float4*)&be[d0];
        float4 e1 = *(const float4*)&be[d0 + 4];
        float4 o0, o1;
        o0.x = (v[0] - mu) * rs * g0.x + e0.x;
        o0.y = (v[1] - mu) * rs * g0.y + e0.y;
        o0.z = (v[2] - mu) * rs * g0.z + e0.z;
        o0.w = (v[3] - mu) * rs * g0.w + e0.w;
        o1.x = (v[4] - mu) * rs * g1.x + e1.x;
        o1.y = (v[5] - mu) * rs * g1.y + e1.y;
        o1.z = (v[6] - mu) * rs * g1.z + e1.z;
        o1.w = (v[7] - mu) * rs * g1.w + e1.w;
        *(float4*)&g_h[base] = o0;
        *(float4*)&g_h[base + 4] = o1;
    }
}

// ---------------- pooling ----------------
__global__ void pool_clear()
{
    int idx = blockIdx.x * blockDim.x + threadIdx.x;
    if (idx < Gq * Hq) { g_psum[idx] = 0.f; g_pmax[idx] = -INFINITY; }
    if (idx < Gq) g_gcnt[idx] = 0.f;
}

__global__ void pool_chunk(const int* __restrict__ n2g)
{
    __shared__ int sg[256];
    int d  = threadIdx.x;
    int n0 = blockIdx.x * 256;
    int n1 = n0 + 256; if (n1 > Nn) n1 = Nn;
    int cn = n1 - n0;
    for (int i = d; i < cn; i += 128) sg[i] = n2g[n0 + i];
    __syncthreads();

    int   curg = sg[0];
    float sum = 0.f, mx = -INFINITY;
    int   cnt = 0;
    for (int j = 0; j < cn; j++) {
        int g = sg[j];
        if (g != curg) {
            atomicAdd(&g_psum[curg * Hq + d], sum);
            atomicMaxFloat(&g_pmax[curg * Hq + d], mx);
            if (d == 0) atomicAdd(&g_gcnt[curg], (float)cnt);
            sum = 0.f; mx = -INFINITY; cnt = 0; curg = g;
        }
        float v = g_h[(size_t)(n0 + j) * Hq + d];
        sum += v; mx = fmaxf(mx, v); cnt++;
    }
    atomicAdd(&g_psum[curg * Hq + d], sum);
    atomicMaxFloat(&g_pmax[curg * Hq + d], mx);
    if (d == 0) atomicAdd(&g_gcnt[curg], (float)cnt);
}

// ---------------- final MLP head ----------------
__global__ void final_mlp(const float* __restrict__ Wq1, const float* __restrict__ bq1,
                          const float* __restrict__ gq, const float* __restrict__ beq,
                          const float* __restrict__ Wq2, const float* __restrict__ bq2,
                          float* __restrict__ out)
{
    int g = blockIdx.x;
    int tid = threadIdx.x;   // 256
    __shared__ float emb[2 * Hq];
    __shared__ float p[Hq];
    __shared__ float stats[2];

    if (tid < Hq) emb[tid] = g_psum[g * Hq + tid] / fmaxf(g_gcnt[g], 1.0f);
    else          emb[tid] = g_pmax[g * Hq + (tid - Hq)];
    __syncthreads();

    if (tid < Hq) {
        float t = bq1[tid];
        for (int k = 0; k < 2 * Hq; k++) t += emb[k] * Wq1[k * Hq + tid];
        p[tid] = t;
    }
    __syncthreads();

    if (tid == 0) {
        float s = 0.f;
        for (int j = 0; j < Hq; j++) s += p[j];
        float mu = s * (1.0f / 128.0f);
        float v = 0.f;
        for (int j = 0; j < Hq; j++) { float dd = p[j] - mu; v += dd * dd; }
        stats[0] = mu;
        stats[1] = rsqrtf(v * (1.0f / 128.0f) + 1e-5f);
    }
    __syncthreads();

    if (tid < Hq) {
        float y = (p[tid] - stats[0]) * stats[1] * gq[tid] + beq[tid];
        p[tid] = gelu_exact(y);
    }
    __syncthreads();

    float o = bq2[tid];
    for (int k = 0; k < Hq; k++) o += p[k] * Wq2[k * FOUTq + tid];
    out[g * FOUTq + tid] = o;
}

// ---------------- launch ----------------
extern "C" void kernel_launch(void* const* d_in, const int* in_sizes, int n_in,
                              void* d_out, int out_size)
{
    const float* x   = (const float*)d_in[0];
    const int*   ei  = (const int*)d_in[1];
    const int*   n2g = (const int*)d_in[2];
    const float* Wp  = (const float*)d_in[3];
    const float* bp  = (const float*)d_in[4];
    const float* Wq1 = (const float*)d_in[5];
    const float* bq1 = (const float*)d_in[6];
    const float* gq  = (const float*)d_in[7];
    const float* beq = (const float*)d_in[8];
    const float* Wq2 = (const float*)d_in[9];
    const float* bq2 = (const float*)d_in[10];
    float* out = (float*)d_out;

    float* ph = nullptr;
    cudaGetSymbolAddress((void**)&ph, g_h);

    // dynamic smem size for fused kernel
    const int FUSED_SMEM = (128 * AUP + 32 * 136) * 4;   // 85,376 bytes

    static cudaStream_t s2 = nullptr;
    static cudaEvent_t evG = nullptr, evB = nullptr, evC = nullptr;
    if (s2 == nullptr) {
        cudaStreamCreateWithFlags(&s2, cudaStreamNonBlocking);
        cudaEventCreateWithFlags(&evG, cudaEventDisableTiming);
        cudaEventCreateWithFlags(&evB, cudaEventDisableTiming);
        cudaEventCreateWithFlags(&evC, cudaEventDisableTiming);
        cudaFuncSetAttribute(gemm_fused0,
                             cudaFuncAttributeMaxDynamicSharedMemorySize, FUSED_SMEM);
    }

    const int NB_GEMM = (Nn + 127) / 128;
    const int NB_E    = (ETOT + 255) / 256;
    const int NB_AGG  = Nn / 8;
    const int NB_POOL = (Nn + 255) / 256;

    // kernel 1: fused proj + layer0 GEMM + histogram
    gemm_fused0<<<NB_GEMM, 256, FUSED_SMEM>>>(
        x, Wp, bp, (const float*)d_in[11],
        (const float*)d_in[12], (const float*)d_in[13], ei, Nn);
    cudaEventRecord(evG, 0);

    // kernels 2-3: scan + fill on side stream (after histogram complete)
    cudaStreamWaitEvent(s2, evG, 0);
    scan_dl<<<NTILE, 256, 0, s2>>>();
    csr_fill<<<NB_E, 256, 0, s2>>>(ei);
    cudaEventRecord(evB, s2);

    // kernel 4 (PROFILED): layer-0 aggregation
    cudaStreamWaitEvent(0, evB, 0);
    gat_agg_ln<<<NB_AGG, 256>>>((const float*)d_in[14], (const float*)d_in[15],
                                (const float*)d_in[16]);

    // layer 1
    gemm_tf32<<<NB_GEMM, 256>>>(ph, (const float*)d_in[17],
                                (const float*)d_in[18], (const float*)d_in[19], Nn);
    gat_agg_ln<<<NB_AGG, 256>>>((const float*)d_in[20], (const float*)d_in[21],
                                (const float*)d_in[22]);

    // pooling + head
    pool_clear<<<(Gq * Hq + 255) / 256, 256, 0, s2>>>();
    cudaEventRecord(evC, s2);
    cudaStreamWaitEvent(0, evC, 0);
    pool_chunk<<<NB_POOL, 128>>>(n2g);
    final_mlp<<<Gq, 256>>>(Wq1, bq1, gq, beq, Wq2, bq2, out);
}

// round 13
// speedup vs baseline: 1.1474x; 1.1474x over previous
#include <cuda_runtime.h>
#include <cuda_bf16.h>
#include <math.h>

#define Nn   100000
#define Ee   1600000
#define ETOT (Ee + Nn)
#define DINq 16
#define Hq   128
#define HEADSq 4
#define Gq   64
#define FOUTq 256
#define NTILE ((Nn + 255) / 256)

typedef unsigned long long u64;
typedef unsigned int u32;

// ---- scratch (static device memory) ----
__device__ float g_h[(size_t)Nn * Hq];
__device__ u32   g_hpb[(size_t)Nn * (Hq / 2)];
__device__ float g_alS[Nn * HEADSq];
__device__ float g_alD[Nn * HEADSq];
__device__ int   g_cnt_i[Nn];
__device__ int   g_rowptr[Nn + 1];
__device__ int   g_cursor[Nn];
__device__ int   g_csr_src[ETOT];
__device__ u64   g_tstat[NTILE];
__device__ float g_psum[Gq * Hq];
__device__ float g_pmax[Gq * Hq];
__device__ float g_gcnt[Gq];

#define FLAG_AGG (1ull << 62)
#define FLAG_INC (1ull << 63)

__device__ __forceinline__ void atomicMaxFloat(float* addr, float v) {
    if (v >= 0.0f) atomicMax((int*)addr, __float_as_int(v));
    else           atomicMin((unsigned int*)addr, __float_as_uint(v));
}

__device__ __forceinline__ float gelu_exact(float v) {
    return 0.5f * v * (1.0f + erff(v * 0.70710678118654752f));
}

__device__ __forceinline__ u32 bfpack(float lo, float hi) {
    u32 r; asm("cvt.rn.bf16x2.f32 %0, %1, %2;" : "=r"(r) : "f"(hi), "f"(lo)); return r;
}

__device__ __forceinline__ u32 tf32cvt(float f) {
    u32 r; asm("cvt.rna.tf32.f32 %0, %1;" : "=r"(r) : "f"(f)); return r;
}

__device__ __forceinline__ void mma_tf32(float* c, const u32* a, u32 b0, u32 b1) {
    asm volatile("mma.sync.aligned.m16n8k8.row.col.f32.tf32.tf32.f32 "
        "{%0,%1,%2,%3}, {%4,%5,%6,%7}, {%8,%9}, {%0,%1,%2,%3};"
        : "+f"(c[0]), "+f"(c[1]), "+f"(c[2]), "+f"(c[3])
        : "r"(a[0]), "r"(a[1]), "r"(a[2]), "r"(a[3]), "r"(b0), "r"(b1));
}

// ---- packed f32x2 helpers ----
__device__ __forceinline__ void pfma(u64& d, u64 a, u64 b) {
    asm("fma.rn.f32x2 %0, %1, %2, %0;" : "+l"(d) : "l"(a), "l"(b));
}
__device__ __forceinline__ u64 pku(u32 lo, u32 hi) {
    u64 r; asm("mov.b64 %0, {%1,%2};" : "=l"(r) : "r"(lo), "r"(hi)); return r;
}
__device__ __forceinline__ u64 pkf(float lo, float hi) {
    u64 r; asm("mov.b64 %0, {%1,%2};" : "=l"(r) : "f"(lo), "f"(hi)); return r;
}
__device__ __forceinline__ u64 swap64(u64 p) { return pku((u32)(p >> 32), (u32)p); }
__device__ __forceinline__ float lo32(u64 p) { return __uint_as_float((u32)p); }
__device__ __forceinline__ float hi32(u64 p) { return __uint_as_float((u32)(p >> 32)); }
// bf16x2 word -> packed f32x2 (lo in low word, hi in high word)
__device__ __forceinline__ u64 bfexpand(u32 w) {
    return pku(w << 16, w & 0xffff0000u);
}

// ------- proj GEMM (K=16): h = gelu(x @ Wp + bp), FFMA2 -------
__global__ void gemm_proj(const float* __restrict__ A, const float* __restrict__ W,
                          const float* __restrict__ bias, float* __restrict__ C, int M)
{
    const int BN = 128, BK = 16;
    __shared__ float As[BK][BN + 4];
    __shared__ float Ws[BK][Hq + 4];
    int tid = threadIdx.x;
    int tx = tid & 15, ty = tid >> 4;
    int m0 = blockIdx.x * BN;
    int c0 = tx * 8;
    int r0 = ty * 8;

    u64 acc[4][4][2];
#pragma unroll
    for (int rp = 0; rp < 4; rp++)
#pragma unroll
        for (int cp = 0; cp < 4; cp++) { acc[rp][cp][0] = 0ull; acc[rp][cp][1] = 0ull; }

#pragma unroll
    for (int i = tid; i < BN * BK; i += 256) {
        int r = i >> 4, k = i & 15;
        As[k][r] = (m0 + r < M) ? A[(size_t)(m0 + r) * DINq + k] : 0.f;
    }
#pragma unroll
    for (int i = tid; i < BK * Hq; i += 256) {
        int k = i >> 7, c = i & 127;
        Ws[k][c] = W[(size_t)k * Hq + c];
    }
    __syncthreads();
#pragma unroll
    for (int kk = 0; kk < BK; kk++) {
        ulonglong2 ra = *(const ulonglong2*)&As[kk][r0];
        ulonglong2 rb = *(const ulonglong2*)&As[kk][r0 + 4];
        ulonglong2 wa = *(const ulonglong2*)&Ws[kk][c0];
        ulonglong2 wb = *(const ulonglong2*)&Ws[kk][c0 + 4];
        u64 rr[4] = {ra.x, ra.y, rb.x, rb.y};
        u64 cn[4] = {wa.x, wa.y, wb.x, wb.y};
        u64 cs[4] = {swap64(wa.x), swap64(wa.y), swap64(wb.x), swap64(wb.y)};
#pragma unroll
        for (int rp = 0; rp < 4; rp++)
#pragma unroll
            for (int cp = 0; cp < 4; cp++) {
                pfma(acc[rp][cp][0], rr[rp], cn[cp]);
                pfma(acc[rp][cp][1], rr[rp], cs[cp]);
            }
    }

    float v[8][8];
#pragma unroll
    for (int rp = 0; rp < 4; rp++)
#pragma unroll
        for (int cp = 0; cp < 4; cp++) {
            v[2 * rp][2 * cp]         = lo32(acc[rp][cp][0]);
            v[2 * rp + 1][2 * cp + 1] = hi32(acc[rp][cp][0]);
            v[2 * rp][2 * cp + 1]     = lo32(acc[rp][cp][1]);
            v[2 * rp + 1][2 * cp]     = hi32(acc[rp][cp][1]);
        }

    float b8[8];
#pragma unroll
    for (int q = 0; q < 8; q++) b8[q] = bias[c0 + q];
#pragma unroll
    for (int r = 0; r < 8; r++) {
        int m = m0 + r0 + r;
        if (m < M) {
#pragma unroll
            for (int q = 0; q < 8; q++) v[r][q] = gelu_exact(v[r][q] + b8[q]);
            float4 o0 = make_float4(v[r][0], v[r][1], v[r][2], v[r][3]);
            float4 o1 = make_float4(v[r][4], v[r][5], v[r][6], v[r][7]);
            *(float4*)&C[(size_t)m * Hq + c0] = o0;
            *(float4*)&C[(size_t)m * Hq + c0 + 4] = o1;
        }
    }
}

// ------- layer GEMM: tf32 tensor cores; bf16 hp out + fused attn logits -------
__global__ void gemm_tf32(const float* __restrict__ A, const float* __restrict__ W,
                          const float* __restrict__ a_s, const float* __restrict__ a_d, int M)
{
    __shared__ u32 Au[128][36];
    __shared__ u32 Wu[32][136];
    int tid = threadIdx.x;
    int w = tid >> 5, lane = tid & 31;
    int wr = w >> 1, wc = w & 1;
    int q = lane & 3, g = lane >> 2;
    int m0 = blockIdx.x * 128;

    float c[2][8][4];
#pragma unroll
    for (int mt = 0; mt < 2; mt++)
#pragma unroll
        for (int nt = 0; nt < 8; nt++)
#pragma unroll
            for (int f = 0; f < 4; f++) c[mt][nt][f] = 0.f;

    for (int kc = 0; kc < 128; kc += 32) {
#pragma unroll
        for (int it = 0; it < 4; it++) {
            int idx = (it * 256 + tid) * 4;
            int r = idx >> 5, cI = idx & 31;
            float4 v4 = make_float4(0.f, 0.f, 0.f, 0.f);
            if (m0 + r < M) v4 = *(const float4*)&A[(size_t)(m0 + r) * Hq + kc + cI];
            Au[r][cI + 0] = tf32cvt(v4.x);
            Au[r][cI + 1] = tf32cvt(v4.y);
            Au[r][cI + 2] = tf32cvt(v4.z);
            Au[r][cI + 3] = tf32cvt(v4.w);
        }
#pragma unroll
        for (int it = 0; it < 4; it++) {
            int idx = (it * 256 + tid) * 4;
            int r = idx >> 7, cI = idx & 127;
            float4 v4 = *(const float4*)&W[(size_t)(kc + r) * Hq + cI];
            Wu[r][cI + 0] = tf32cvt(v4.x);
            Wu[r][cI + 1] = tf32cvt(v4.y);
            Wu[r][cI + 2] = tf32cvt(v4.z);
            Wu[r][cI + 3] = tf32cvt(v4.w);
        }
        __syncthreads();
#pragma unroll
        for (int kt = 0; kt < 32; kt += 8) {
            u32 af[2][4];
#pragma unroll
            for (int mt = 0; mt < 2; mt++) {
                int r = wr * 32 + mt * 16;
                af[mt][0] = Au[r + g][kt + q];
                af[mt][1] = Au[r + g + 8][kt + q];
                af[mt][2] = Au[r + g][kt + q + 4];
                af[mt][3] = Au[r + g + 8][kt + q + 4];
            }
#pragma unroll
            for (int nt = 0; nt < 8; nt++) {
                int n = wc * 64 + nt * 8 + g;
                u32 b0 = Wu[kt + q][n];
                u32 b1 = Wu[kt + q + 4][n];
                mma_tf32(c[0][nt], af[0], b0, b1);
                mma_tf32(c[1][nt], af[1], b0, b1);
            }
        }
        __syncthreads();
    }

#pragma unroll
    for (int mt = 0; mt < 2; mt++)
#pragma unroll
        for (int half = 0; half < 2; half++) {
            int m = m0 + wr * 32 + mt * 16 + g + half * 8;
            if (m < M) {
#pragma unroll
                for (int nt = 0; nt < 8; nt++) {
                    u32 pw = bfpack(c[mt][nt][2 * half], c[mt][nt][2 * half + 1]);
                    g_hpb[(size_t)m * (Hq / 2) + wc * 32 + nt * 4 + q] = pw;
                }
            }
        }

    float asv[8][2], adv[8][2];
#pragma unroll
    for (int nt = 0; nt < 8; nt++) {
        int col = wc * 64 + nt * 8 + 2 * q;
        asv[nt][0] = a_s[col];     asv[nt][1] = a_s[col + 1];
        adv[nt][0] = a_d[col];     adv[nt][1] = a_d[col + 1];
    }
#pragma unroll
    for (int mt = 0; mt < 2; mt++)
#pragma unroll
        for (int half = 0; half < 2; half++) {
            int m = m0 + wr * 32 + mt * 16 + g + half * 8;
            float ps0 = 0.f, ps1 = 0.f, pd0 = 0.f, pd1 = 0.f;
#pragma unroll
            for (int nt = 0; nt < 8; nt++) {
                float x0 = c[mt][nt][2 * half], x1 = c[mt][nt][2 * half + 1];
                float s = x0 * asv[nt][0] + x1 * asv[nt][1];
                float d = x0 * adv[nt][0] + x1 * adv[nt][1];
                if (nt < 4) { ps0 += s; pd0 += d; }
                else        { ps1 += s; pd1 += d; }
            }
            ps0 += __shfl_xor_sync(0xffffffffu, ps0, 1);
            ps1 += __shfl_xor_sync(0xffffffffu, ps1, 1);
            pd0 += __shfl_xor_sync(0xffffffffu, pd0, 1);
            pd1 += __shfl_xor_sync(0xffffffffu, pd1, 1);
            ps0 += __shfl_xor_sync(0xffffffffu, ps0, 2);
            ps1 += __shfl_xor_sync(0xffffffffu, ps1, 2);
            pd0 += __shfl_xor_sync(0xffffffffu, pd0, 2);
            pd1 += __shfl_xor_sync(0xffffffffu, pd1, 2);
            if (q == 0 && m < M) {
                int hb = wc * 2;
                g_alS[m * 4 + hb]     = ps0;
                g_alS[m * 4 + hb + 1] = ps1;
                g_alD[m * 4 + hb]     = pd0;
                g_alD[m * 4 + hb + 1] = pd1;
            }
        }
}

// ================= CSR build =================
__global__ void hist_dst(const int* __restrict__ ei)
{
    int e = blockIdx.x * blockDim.x + threadIdx.x;
    if (e < NTILE) g_tstat[e] = 0;
    if (e >= ETOT) return;
    int d = (e < Ee) ? ei[Ee + e] : (e - Ee);
    atomicAdd(&g_cnt_i[d], 1);
}

__global__ void scan_dl()
{
    __shared__ int s[256];
    __shared__ int s_prefix;
    int bid = blockIdx.x, tid = threadIdx.x;
    int i = bid * 256 + tid;
    int v = (i < Nn) ? g_cnt_i[i] : 0;
    s[tid] = v;
    __syncthreads();
#pragma unroll
    for (int o = 1; o < 256; o <<= 1) {
        int t = (tid >= o) ? s[tid - o] : 0;
        __syncthreads();
        s[tid] += t;
        __syncthreads();
    }
    int incl = s[tid];
    int agg  = s[255];

    if (tid == 0) {
        u64 pub = (bid == 0) ? (FLAG_INC | (u64)(u32)agg) : (FLAG_AGG | (u64)(u32)agg);
        atomicExch((unsigned long long*)&g_tstat[bid], pub);
        if (bid == 0) s_prefix = 0;
    }

    if (bid > 0 && tid < 32) {
        int lane = tid;
        u32 running = 0;
        int look = bid - 1;
        while (true) {
            int t = look - lane;
            u64 st;
            if (t >= 0) {
                do { st = *(volatile u64*)&g_tstat[t]; } while (st == 0);
            } else {
                st = FLAG_INC;
            }
            u32 incm = __ballot_sync(0xffffffffu, (st & FLAG_INC) != 0);
            u32 val;
            if (incm) {
                int L = __ffs(incm) - 1;
                val = (lane <= L) ? (u32)st : 0;
            } else {
                val = (u32)st;
            }
#pragma unroll
            for (int o = 16; o; o >>= 1) val += __shfl_xor_sync(0xffffffffu, val, o);
            running += val;
            if (incm) break;
            look -= 32;
        }
        if (lane == 0) {
            atomicExch((unsigned long long*)&g_tstat[bid],
                       FLAG_INC | (u64)(u32)(running + (u32)agg));
            s_prefix = (int)running;
        }
    }
    __syncthreads();

    int pre = s_prefix;
    if (i < Nn) {
        int r = pre + incl - v;
        g_rowptr[i] = r;
        g_cursor[i] = r;
    }
    if (i == 0) g_rowptr[Nn] = ETOT;
}

__global__ void csr_fill(const int* __restrict__ ei)
{
    int e = blockIdx.x * blockDim.x + threadIdx.x;
    if (e >= ETOT) return;
    int s, d;
    if (e < Ee) { s = ei[e]; d = ei[Ee + e]; } else { s = d = e - Ee; }
    int pos = atomicAdd(&g_cursor[d], 1);
    g_csr_src[pos] = s;
}

// == GAT aggregation: warp per node, half-warp per edge, packed f32x2 FMA ==
__global__ void gat_agg_ln(const float* __restrict__ bg, const float* __restrict__ ga,
                           const float* __restrict__ be)
{
    int n = blockIdx.x * 8 + (threadIdx.x >> 5);
    if (n >= Nn) return;
    int lane = threadIdx.x & 31;
    int pairlane = lane >> 4;
    int sub = lane & 15;
    int head = sub >> 2;

    int start = g_rowptr[n];
    int end   = g_rowptr[n + 1];
    float adh = g_alD[n * 4 + head];

    u64 acc[4];
#pragma unroll
    for (int k = 0; k < 4; k++) acc[k] = 0ull;
    float den = 0.f;

    int i = start;
    for (; i + 4 <= end; i += 4) {
        int sA = g_csr_src[i + pairlane];
        int sB = g_csr_src[i + 2 + pairlane];
        float lA = g_alS[sA * 4 + head] + adh;
        float lB = g_alS[sB * 4 + head] + adh;
        lA = (lA > 0.f) ? lA : 0.2f * lA;
        lB = (lB > 0.f) ? lB : 0.2f * lB;
        float eA = __expf(lA);
        float eB = __expf(lB);
        uint4 pA = *(const uint4*)&g_hpb[(size_t)sA * 64 + sub * 4];
        uint4 pB = *(const uint4*)&g_hpb[(size_t)sB * 64 + sub * 4];
        den += eA + eB;
        u64 eAp = pkf(eA, eA);
        u64 eBp = pkf(eB, eB);
        pfma(acc[0], eAp, bfexpand(pA.x));
        pfma(acc[1], eAp, bfexpand(pA.y));
        pfma(acc[2], eAp, bfexpand(pA.z));
        pfma(acc[3], eAp, bfexpand(pA.w));
        pfma(acc[0], eBp, bfexpand(pB.x));
        pfma(acc[1], eBp, bfexpand(pB.y));
        pfma(acc[2], eBp, bfexpand(pB.z));
        pfma(acc[3], eBp, bfexpand(pB.w));
    }
    for (; i + 2 <= end; i += 2) {
        int sA = g_csr_src[i + pairlane];
        float lA = g_alS[sA * 4 + head] + adh;
        lA = (lA > 0.f) ? lA : 0.2f * lA;
        float eA = __expf(lA);
        uint4 pA = *(const uint4*)&g_hpb[(size_t)sA * 64 + sub * 4];
        den += eA;
        u64 eAp = pkf(eA, eA);
        pfma(acc[0], eAp, bfexpand(pA.x));
        pfma(acc[1], eAp, bfexpand(pA.y));
        pfma(acc[2], eAp, bfexpand(pA.z));
        pfma(acc[3], eAp, bfexpand(pA.w));
    }
    if (i < end) {
        int sA = g_csr_src[i];
        float lA = g_alS[sA * 4 + head] + adh;
        lA = (lA > 0.f) ? lA : 0.2f * lA;
        float eA = (pairlane == 0) ? __expf(lA) : 0.f;
        uint4 pA = *(const uint4*)&g_hpb[(size_t)sA * 64 + sub * 4];
        den += eA;
        u64 eAp = pkf(eA, eA);
        pfma(acc[0], eAp, bfexpand(pA.x));
        pfma(acc[1], eAp, bfexpand(pA.y));
        pfma(acc[2], eAp, bfexpand(pA.z));
        pfma(acc[3], eAp, bfexpand(pA.w));
    }

    float a[8];
#pragma unroll
    for (int k = 0; k < 4; k++) { a[2 * k] = lo32(acc[k]); a[2 * k + 1] = hi32(acc[k]); }

    // combine the two halves (same dims, different edge subsets)
    den += __shfl_xor_sync(0xffffffffu, den, 16);
#pragma unroll
    for (int k = 0; k < 8; k++) a[k] += __shfl_xor_sync(0xffffffffu, a[k], 16);

    float dinv = 1.0f / (den + 1e-16f);

    int d0 = sub * 8;
    size_t base = (size_t)n * Hq + d0;
    float4 h0 = *(const float4*)&g_h[base];
    float4 h1 = *(const float4*)&g_h[base + 4];
    float4 b0 = *(const float4*)&bg[d0];
    float4 b1 = *(const float4*)&bg[d0 + 4];
    float v[8];
    v[0] = a[0] * dinv + b0.x + h0.x;
    v[1] = a[1] * dinv + b0.y + h0.y;
    v[2] = a[2] * dinv + b0.z + h0.z;
    v[3] = a[3] * dinv + b0.w + h0.w;
    v[4] = a[4] * dinv + b1.x + h1.x;
    v[5] = a[5] * dinv + b1.y + h1.y;
    v[6] = a[6] * dinv + b1.z + h1.z;
    v[7] = a[7] * dinv + b1.w + h1.w;

    float s = 0.f, t = 0.f;
#pragma unroll
    for (int k = 0; k < 8; k++) { s += v[k]; t += v[k] * v[k]; }
#pragma unroll
    for (int o = 8; o; o >>= 1) {
        s += __shfl_xor_sync(0xffffffffu, s, o);
        t += __shfl_xor_sync(0xffffffffu, t, o);
    }
    float mu = s * (1.0f / 128.0f);
    float var = t * (1.0f / 128.0f) - mu * mu;
    float rs = rsqrtf(var + 1e-5f);

    if (pairlane == 0) {
        float4 g0 = *(const float4*)&ga[d0];
        float4 g1 = *(const float4*)&ga[d0 + 4];
        float4 e0 = *(const float4*)&be[d0];
        float4 e1 = *(const float4*)&be[d0 + 4];
        float4 o0, o1;
        o0.x = (v[0] - mu) * rs * g0.x + e0.x;
        o0.y = (v[1] - mu) * rs * g0.y + e0.y;
        o0.z = (v[2] - mu) * rs * g0.z + e0.z;
        o0.w = (v[3] - mu) * rs * g0.w + e0.w;
        o1.x = (v[4] - mu) * rs * g1.x + e1.x;
        o1.y = (v[5] - mu) * rs * g1.y + e1.y;
        o1.z = (v[6] - mu) * rs * g1.z + e1.z;
        o1.w = (v[7] - mu) * rs * g1.w + e1.w;
        *(float4*)&g_h[base] = o0;
        *(float4*)&g_h[base + 4] = o1;
    }
}

// ---------------- pooling ----------------
__global__ void pool_clear()
{
    int idx = blockIdx.x * blockDim.x + threadIdx.x;
    if (idx < Gq * Hq) { g_psum[idx] = 0.f; g_pmax[idx] = -INFINITY; }
    if (idx < Gq) g_gcnt[idx] = 0.f;
}

__global__ void pool_chunk(const int* __restrict__ n2g)
{
    __shared__ int sg[256];
    int d  = threadIdx.x;
    int n0 = blockIdx.x * 256;
    int n1 = n0 + 256; if (n1 > Nn) n1 = Nn;
    int cn = n1 - n0;
    for (int i = d; i < cn; i += 128) sg[i] = n2g[n0 + i];
    __syncthreads();

    int   curg = sg[0];
    float sum = 0.f, mx = -INFINITY;
    int   cnt = 0;
    for (int j = 0; j < cn; j++) {
        int g = sg[j];
        if (g != curg) {
            atomicAdd(&g_psum[curg * Hq + d], sum);
            atomicMaxFloat(&g_pmax[curg * Hq + d], mx);
            if (d == 0) atomicAdd(&g_gcnt[curg], (float)cnt);
            sum = 0.f; mx = -INFINITY; cnt = 0; curg = g;
        }
        float v = g_h[(size_t)(n0 + j) * Hq + d];
        sum += v; mx = fmaxf(mx, v); cnt++;
    }
    atomicAdd(&g_psum[curg * Hq + d], sum);
    atomicMaxFloat(&g_pmax[curg * Hq + d], mx);
    if (d == 0) atomicAdd(&g_gcnt[curg], (float)cnt);
}

// ---------------- final MLP head ----------------
__global__ void final_mlp(const float* __restrict__ Wq1, const float* __restrict__ bq1,
                          const float* __restrict__ gq, const float* __restrict__ beq,
                          const float* __restrict__ Wq2, const float* __restrict__ bq2,
                          float* __restrict__ out)
{
    int g = blockIdx.x;
    int tid = threadIdx.x;   // 256
    __shared__ float emb[2 * Hq];
    __shared__ float p[Hq];
    __shared__ float stats[2];

    if (tid < Hq) emb[tid] = g_psum[g * Hq + tid] / fmaxf(g_gcnt[g], 1.0f);
    else          emb[tid] = g_pmax[g * Hq + (tid - Hq)];
    __syncthreads();

    if (tid < Hq) {
        float t = bq1[tid];
        for (int k = 0; k < 2 * Hq; k++) t += emb[k] * Wq1[k * Hq + tid];
        p[tid] = t;
    }
    __syncthreads();

    if (tid == 0) {
        float s = 0.f;
        for (int j = 0; j < Hq; j++) s += p[j];
        float mu = s * (1.0f / 128.0f);
        float v = 0.f;
        for (int j = 0; j < Hq; j++) { float dd = p[j] - mu; v += dd * dd; }
        stats[0] = mu;
        stats[1] = rsqrtf(v * (1.0f / 128.0f) + 1e-5f);
    }
    __syncthreads();

    if (tid < Hq) {
        float y = (p[tid] - stats[0]) * stats[1] * gq[tid] + beq[tid];
        p[tid] = gelu_exact(y);
    }
    __syncthreads();

    float o = bq2[tid];
    for (int k = 0; k < Hq; k++) o += p[k] * Wq2[k * FOUTq + tid];
    out[g * FOUTq + tid] = o;
}

// ---------------- launch ----------------
extern "C" void kernel_launch(void* const* d_in, const int* in_sizes, int n_in,
                              void* d_out, int out_size)
{
    const float* x   = (const float*)d_in[0];
    const int*   ei  = (const int*)d_in[1];
    const int*   n2g = (const int*)d_in[2];
    const float* Wp  = (const float*)d_in[3];
    const float* bp  = (const float*)d_in[4];
    const float* Wq1 = (const float*)d_in[5];
    const float* bq1 = (const float*)d_in[6];
    const float* gq  = (const float*)d_in[7];
    const float* beq = (const float*)d_in[8];
    const float* Wq2 = (const float*)d_in[9];
    const float* bq2 = (const float*)d_in[10];
    float* out = (float*)d_out;

    float* ph = nullptr;
    void* pcnt = nullptr;
    cudaGetSymbolAddress((void**)&ph, g_h);
    cudaGetSymbolAddress(&pcnt, g_cnt_i);

    static cudaStream_t s2 = nullptr;
    static cudaEvent_t evA = nullptr, evB = nullptr, evC = nullptr;
    if (s2 == nullptr) {
        cudaStreamCreateWithFlags(&s2, cudaStreamNonBlocking);
        cudaEventCreateWithFlags(&evA, cudaEventDisableTiming);
        cudaEventCreateWithFlags(&evB, cudaEventDisableTiming);
        cudaEventCreateWithFlags(&evC, cudaEventDisableTiming);
    }

    const int NB_GEMM = (Nn + 127) / 128;
    const int NB_E    = (ETOT + 255) / 256;
    const int NB_AGG  = Nn / 8;
    const int NB_POOL = (Nn + 255) / 256;

    // ---- side stream: CSR build (overlaps with proj + layer-0 GEMM) ----
    cudaEventRecord(evA, 0);
    cudaStreamWaitEvent(s2, evA, 0);
    cudaMemsetAsync(pcnt, 0, Nn * sizeof(int), s2);

    gemm_proj<<<NB_GEMM, 256>>>(x, Wp, bp, ph, Nn);
    hist_dst<<<NB_E, 256, 0, s2>>>(ei);
    scan_dl<<<NTILE, 256, 0, s2>>>();
    csr_fill<<<NB_E, 256, 0, s2>>>(ei);
    cudaEventRecord(evB, s2);

    gemm_tf32<<<NB_GEMM, 256>>>(ph, (const float*)d_in[11],
                                (const float*)d_in[12], (const float*)d_in[13], Nn);

    cudaStreamWaitEvent(0, evB, 0);
    gat_agg_ln<<<NB_AGG, 256>>>((const float*)d_in[14], (const float*)d_in[15],
                                (const float*)d_in[16]);

    gemm_tf32<<<NB_GEMM, 256>>>(ph, (const float*)d_in[17],
                                (const float*)d_in[18], (const float*)d_in[19], Nn);
    gat_agg_ln<<<NB_AGG, 256>>>((const float*)d_in[20], (const float*)d_in[21],
                                (const float*)d_in[22]);

    pool_clear<<<(Gq * Hq + 255) / 256, 256, 0, s2>>>();
    cudaEventRecord(evC, s2);
    cudaStreamWaitEvent(0, evC, 0);
    pool_chunk<<<NB_POOL, 128>>>(n2g);
    final_mlp<<<Gq, 256>>>(Wq1, bq1, gq, beq, Wq2, bq2, out);
}

// round 14
// speedup vs baseline: 1.1891x; 1.0364x over previous
#include <cuda_runtime.h>
#include <cuda_bf16.h>
#include <math.h>

#define Nn   100000
#define Ee   1600000
#define ETOT (Ee + Nn)
#define DINq 16
#define Hq   128
#define HEADSq 4
#define Gq   64
#define FOUTq 256
#define NTILE ((Nn + 255) / 256)

typedef unsigned long long u64;
typedef unsigned int u32;

// ---- scratch (static device memory) ----
__device__ float g_h[(size_t)Nn * Hq];
__device__ u32   g_hpb[(size_t)Nn * (Hq / 2)];
__device__ float g_alS[Nn * HEADSq];
__device__ float g_alD[Nn * HEADSq];
__device__ int   g_cnt_i[Nn];
__device__ int   g_rowptr[Nn + 1];
__device__ int   g_cursor[Nn];
__device__ int   g_csr_src[ETOT];
__device__ u64   g_tstat[NTILE];
__device__ float g_psum[Gq * Hq];
__device__ float g_pmax[Gq * Hq];
__device__ float g_gcnt[Gq];

#define FLAG_AGG (1ull << 62)
#define FLAG_INC (1ull << 63)

__device__ __forceinline__ void atomicMaxFloat(float* addr, float v) {
    if (v >= 0.0f) atomicMax((int*)addr, __float_as_int(v));
    else           atomicMin((unsigned int*)addr, __float_as_uint(v));
}

__device__ __forceinline__ float gelu_exact(float v) {
    return 0.5f * v * (1.0f + erff(v * 0.70710678118654752f));
}

// pack two fp32 -> bf16x2 word (lo in low half)
__device__ __forceinline__ u32 bfpack(float lo, float hi) {
    u32 r; asm("cvt.rn.bf16x2.f32 %0, %1, %2;" : "=r"(r) : "f"(hi), "f"(lo)); return r;
}

// bf16 m16n8k16 mma (fp32 accum)
__device__ __forceinline__ void mma_bf16(float* c, const u32* a, u32 b0, u32 b1) {
    asm volatile("mma.sync.aligned.m16n8k16.row.col.f32.bf16.bf16.f32 "
        "{%0,%1,%2,%3}, {%4,%5,%6,%7}, {%8,%9}, {%0,%1,%2,%3};"
        : "+f"(c[0]), "+f"(c[1]), "+f"(c[2]), "+f"(c[3])
        : "r"(a[0]), "r"(a[1]), "r"(a[2]), "r"(a[3]), "r"(b0), "r"(b1));
}

// ---- packed f32x2 helpers ----
__device__ __forceinline__ void pfma(u64& d, u64 a, u64 b) {
    asm("fma.rn.f32x2 %0, %1, %2, %0;" : "+l"(d) : "l"(a), "l"(b));
}
__device__ __forceinline__ u64 pku(u32 lo, u32 hi) {
    u64 r; asm("mov.b64 %0, {%1,%2};" : "=l"(r) : "r"(lo), "r"(hi)); return r;
}
__device__ __forceinline__ u64 pkf(float lo, float hi) {
    u64 r; asm("mov.b64 %0, {%1,%2};" : "=l"(r) : "f"(lo), "f"(hi)); return r;
}
__device__ __forceinline__ u64 swap64(u64 p) { return pku((u32)(p >> 32), (u32)p); }
__device__ __forceinline__ float lo32(u64 p) { return __uint_as_float((u32)p); }
__device__ __forceinline__ float hi32(u64 p) { return __uint_as_float((u32)(p >> 32)); }
// bf16x2 word -> packed f32x2
__device__ __forceinline__ u64 bfexpand(u32 w) {
    return pku(w << 16, w & 0xffff0000u);
}

// ------- proj GEMM (K=16): h = gelu(x @ Wp + bp), FFMA2 -------
__global__ void gemm_proj(const float* __restrict__ A, const float* __restrict__ W,
                          const float* __restrict__ bias, float* __restrict__ C, int M)
{
    const int BN = 128, BK = 16;
    __shared__ float As[BK][BN + 4];
    __shared__ float Ws[BK][Hq + 4];
    int tid = threadIdx.x;
    int tx = tid & 15, ty = tid >> 4;
    int m0 = blockIdx.x * BN;
    int c0 = tx * 8;
    int r0 = ty * 8;

    u64 acc[4][4][2];
#pragma unroll
    for (int rp = 0; rp < 4; rp++)
#pragma unroll
        for (int cp = 0; cp < 4; cp++) { acc[rp][cp][0] = 0ull; acc[rp][cp][1] = 0ull; }

#pragma unroll
    for (int i = tid; i < BN * BK; i += 256) {
        int r = i >> 4, k = i & 15;
        As[k][r] = (m0 + r < M) ? A[(size_t)(m0 + r) * DINq + k] : 0.f;
    }
#pragma unroll
    for (int i = tid; i < BK * Hq; i += 256) {
        int k = i >> 7, c = i & 127;
        Ws[k][c] = W[(size_t)k * Hq + c];
    }
    __syncthreads();
#pragma unroll
    for (int kk = 0; kk < BK; kk++) {
        ulonglong2 ra = *(const ulonglong2*)&As[kk][r0];
        ulonglong2 rb = *(const ulonglong2*)&As[kk][r0 + 4];
        ulonglong2 wa = *(const ulonglong2*)&Ws[kk][c0];
        ulonglong2 wb = *(const ulonglong2*)&Ws[kk][c0 + 4];
        u64 rr[4] = {ra.x, ra.y, rb.x, rb.y};
        u64 cn[4] = {wa.x, wa.y, wb.x, wb.y};
        u64 cs[4] = {swap64(wa.x), swap64(wa.y), swap64(wb.x), swap64(wb.y)};
#pragma unroll
        for (int rp = 0; rp < 4; rp++)
#pragma unroll
            for (int cp = 0; cp < 4; cp++) {
                pfma(acc[rp][cp][0], rr[rp], cn[cp]);
                pfma(acc[rp][cp][1], rr[rp], cs[cp]);
            }
    }

    float v[8][8];
#pragma unroll
    for (int rp = 0; rp < 4; rp++)
#pragma unroll
        for (int cp = 0; cp < 4; cp++) {
            v[2 * rp][2 * cp]         = lo32(acc[rp][cp][0]);
            v[2 * rp + 1][2 * cp + 1] = hi32(acc[rp][cp][0]);
            v[2 * rp][2 * cp + 1]     = lo32(acc[rp][cp][1]);
            v[2 * rp + 1][2 * cp]     = hi32(acc[rp][cp][1]);
        }

    float b8[8];
#pragma unroll
    for (int q = 0; q < 8; q++) b8[q] = bias[c0 + q];
#pragma unroll
    for (int r = 0; r < 8; r++) {
        int m = m0 + r0 + r;
        if (m < M) {
#pragma unroll
            for (int q = 0; q < 8; q++) v[r][q] = gelu_exact(v[r][q] + b8[q]);
            float4 o0 = make_float4(v[r][0], v[r][1], v[r][2], v[r][3]);
            float4 o1 = make_float4(v[r][4], v[r][5], v[r][6], v[r][7]);
            *(float4*)&C[(size_t)m * Hq + c0] = o0;
            *(float4*)&C[(size_t)m * Hq + c0 + 4] = o1;
        }
    }
}

// ------- layer GEMM: bf16 m16n8k16 tensor cores; bf16 hp out + fused attn logits -------
__global__ void gemm_bf16(const float* __restrict__ A, const float* __restrict__ W,
                          const float* __restrict__ a_s, const float* __restrict__ a_d, int M)
{
    __shared__ u32 Au[128][20];   // bf16x2 [m][kp], 16 kp per chunk, pad->stride 20 (conflict-free frags)
    __shared__ u32 Wu[16][132];   // bf16x2 [kp][n]
    int tid = threadIdx.x;
    int w = tid >> 5, lane = tid & 31;
    int wr = w >> 1, wc = w & 1;
    int q = lane & 3, g = lane >> 2;
    int m0 = blockIdx.x * 128;

    float c[2][8][4];
#pragma unroll
    for (int mt = 0; mt < 2; mt++)
#pragma unroll
        for (int nt = 0; nt < 8; nt++)
#pragma unroll
            for (int f = 0; f < 4; f++) c[mt][nt][f] = 0.f;

    for (int kc = 0; kc < 128; kc += 32) {
        // A chunk: 128 rows x 32 k -> packed 128x16 words
#pragma unroll
        for (int it = 0; it < 4; it++) {
            int idx = (it * 256 + tid) * 4;       // float index
            int r = idx >> 5, cI = idx & 31;
            float4 v4 = make_float4(0.f, 0.f, 0.f, 0.f);
            if (m0 + r < M) v4 = *(const float4*)&A[(size_t)(m0 + r) * Hq + kc + cI];
            Au[r][(cI >> 1)]     = bfpack(v4.x, v4.y);
            Au[r][(cI >> 1) + 1] = bfpack(v4.z, v4.w);
        }
        // W chunk: 32 k x 128 n -> packed along k: 16 kp x 128 words
#pragma unroll
        for (int it = 0; it < 2; it++) {
            int widx = (it * 256 + tid) * 4;      // word index
            int kp = widx >> 7, nI = widx & 127;
            float4 r0 = *(const float4*)&W[(size_t)(kc + 2 * kp) * Hq + nI];
            float4 r1 = *(const float4*)&W[(size_t)(kc + 2 * kp + 1) * Hq + nI];
            Wu[kp][nI + 0] = bfpack(r0.x, r1.x);
            Wu[kp][nI + 1] = bfpack(r0.y, r1.y);
            Wu[kp][nI + 2] = bfpack(r0.z, r1.z);
            Wu[kp][nI + 3] = bfpack(r0.w, r1.w);
        }
        __syncthreads();
#pragma unroll
        for (int kh = 0; kh < 2; kh++) {          // two k16 steps per 32-k chunk
            int kp0 = 8 * kh + q;
            u32 af[2][4];
#pragma unroll
            for (int mt = 0; mt < 2; mt++) {
                int r = wr * 32 + mt * 16;
                af[mt][0] = Au[r + g][kp0];
                af[mt][1] = Au[r + g + 8][kp0];
                af[mt][2] = Au[r + g][kp0 + 4];
                af[mt][3] = Au[r + g + 8][kp0 + 4];
            }
#pragma unroll
            for (int nt = 0; nt < 8; nt++) {
                int n = wc * 64 + nt * 8 + g;
                u32 b0 = Wu[kp0][n];
                u32 b1 = Wu[kp0 + 4][n];
                mma_bf16(c[0][nt], af[0], b0, b1);
                mma_bf16(c[1][nt], af[1], b0, b1);
            }
        }
        __syncthreads();
    }

    // epilogue 1: bf16 pack of hp
#pragma unroll
    for (int mt = 0; mt < 2; mt++)
#pragma unroll
        for (int half = 0; half < 2; half++) {
            int m = m0 + wr * 32 + mt * 16 + g + half * 8;
            if (m < M) {
#pragma unroll
                for (int nt = 0; nt < 8; nt++) {
                    u32 pw = bfpack(c[mt][nt][2 * half], c[mt][nt][2 * half + 1]);
                    g_hpb[(size_t)m * (Hq / 2) + wc * 32 + nt * 4 + q] = pw;
                }
            }
        }

    // epilogue 2: attn logits (2 heads per warp)
    float asv[8][2], adv[8][2];
#pragma unroll
    for (int nt = 0; nt < 8; nt++) {
        int col = wc * 64 + nt * 8 + 2 * q;
        asv[nt][0] = a_s[col];     asv[nt][1] = a_s[col + 1];
        adv[nt][0] = a_d[col];     adv[nt][1] = a_d[col + 1];
    }
#pragma unroll
    for (int mt = 0; mt < 2; mt++)
#pragma unroll
        for (int half = 0; half < 2; half++) {
            int m = m0 + wr * 32 + mt * 16 + g + half * 8;
            float ps0 = 0.f, ps1 = 0.f, pd0 = 0.f, pd1 = 0.f;
#pragma unroll
            for (int nt = 0; nt < 8; nt++) {
                float x0 = c[mt][nt][2 * half], x1 = c[mt][nt][2 * half + 1];
                float s = x0 * asv[nt][0] + x1 * asv[nt][1];
                float d = x0 * adv[nt][0] + x1 * adv[nt][1];
                if (nt < 4) { ps0 += s; pd0 += d; }
                else        { ps1 += s; pd1 += d; }
            }
            ps0 += __shfl_xor_sync(0xffffffffu, ps0, 1);
            ps1 += __shfl_xor_sync(0xffffffffu, ps1, 1);
            pd0 += __shfl_xor_sync(0xffffffffu, pd0, 1);
            pd1 += __shfl_xor_sync(0xffffffffu, pd1, 1);
            ps0 += __shfl_xor_sync(0xffffffffu, ps0, 2);
            ps1 += __shfl_xor_sync(0xffffffffu, ps1, 2);
            pd0 += __shfl_xor_sync(0xffffffffu, pd0, 2);
            pd1 += __shfl_xor_sync(0xffffffffu, pd1, 2);
            if (q == 0 && m < M) {
                int hb = wc * 2;
                g_alS[m * 4 + hb]     = ps0;
                g_alS[m * 4 + hb + 1] = ps1;
                g_alD[m * 4 + hb]     = pd0;
                g_alD[m * 4 + hb + 1] = pd1;
            }
        }
}

// ================= CSR build =================
__global__ void hist_dst(const int* __restrict__ ei)
{
    int e = blockIdx.x * blockDim.x + threadIdx.x;
    if (e < NTILE) g_tstat[e] = 0;
    if (e >= ETOT) return;
    int d = (e < Ee) ? ei[Ee + e] : (e - Ee);
    atomicAdd(&g_cnt_i[d], 1);
}

__global__ void scan_dl()
{
    __shared__ int s[256];
    __shared__ int s_prefix;
    int bid = blockIdx.x, tid = threadIdx.x;
    int i = bid * 256 + tid;
    int v = (i < Nn) ? g_cnt_i[i] : 0;
    s[tid] = v;
    __syncthreads();
#pragma unroll
    for (int o = 1; o < 256; o <<= 1) {
        int t = (tid >= o) ? s[tid - o] : 0;
        __syncthreads();
        s[tid] += t;
        __syncthreads();
    }
    int incl = s[tid];
    int agg  = s[255];

    if (tid == 0) {
        u64 pub = (bid == 0) ? (FLAG_INC | (u64)(u32)agg) : (FLAG_AGG | (u64)(u32)agg);
        atomicExch((unsigned long long*)&g_tstat[bid], pub);
        if (bid == 0) s_prefix = 0;
    }

    if (bid > 0 && tid < 32) {
        int lane = tid;
        u32 running = 0;
        int look = bid - 1;
        while (true) {
            int t = look - lane;
            u64 st;
            if (t >= 0) {
                do { st = *(volatile u64*)&g_tstat[t]; } while (st == 0);
            } else {
                st = FLAG_INC;
            }
            u32 incm = __ballot_sync(0xffffffffu, (st & FLAG_INC) != 0);
            u32 val;
            if (incm) {
                int L = __ffs(incm) - 1;
                val = (lane <= L) ? (u32)st : 0;
            } else {
                val = (u32)st;
            }
#pragma unroll
            for (int o = 16; o; o >>= 1) val += __shfl_xor_sync(0xffffffffu, val, o);
            running += val;
            if (incm) break;
            look -= 32;
        }
        if (lane == 0) {
            atomicExch((unsigned long long*)&g_tstat[bid],
                       FLAG_INC | (u64)(u32)(running + (u32)agg));
            s_prefix = (int)running;
        }
    }
    __syncthreads();

    int pre = s_prefix;
    if (i < Nn) {
        int r = pre + incl - v;
        g_rowptr[i] = r;
        g_cursor[i] = r;
    }
    if (i == 0) g_rowptr[Nn] = ETOT;
}

__global__ void csr_fill(const int* __restrict__ ei)
{
    int e = blockIdx.x * blockDim.x + threadIdx.x;
    if (e >= ETOT) return;
    int s, d;
    if (e < Ee) { s = ei[e]; d = ei[Ee + e]; } else { s = d = e - Ee; }
    int pos = atomicAdd(&g_cursor[d], 1);
    g_csr_src[pos] = s;
}

// == GAT aggregation: warp per node, half-warp per edge, packed f32x2 FMA ==
__global__ void gat_agg_ln(const float* __restrict__ bg, const float* __restrict__ ga,
                           const float* __restrict__ be)
{
    int n = blockIdx.x * 8 + (threadIdx.x >> 5);
    if (n >= Nn) return;
    int lane = threadIdx.x & 31;
    int pairlane = lane >> 4;
    int sub = lane & 15;
    int head = sub >> 2;

    int start = g_rowptr[n];
    int end   = g_rowptr[n + 1];
    float adh = g_alD[n * 4 + head];

    u64 acc[4];
#pragma unroll
    for (int k = 0; k < 4; k++) acc[k] = 0ull;
    float den = 0.f;

    int i = start;
    for (; i + 4 <= end; i += 4) {
        int sA = g_csr_src[i + pairlane];
        int sB = g_csr_src[i + 2 + pairlane];
        float lA = g_alS[sA * 4 + head] + adh;
        float lB = g_alS[sB * 4 + head] + adh;
        lA = (lA > 0.f) ? lA : 0.2f * lA;
        lB = (lB > 0.f) ? lB : 0.2f * lB;
        float eA = __expf(lA);
        float eB = __expf(lB);
        uint4 pA = *(const uint4*)&g_hpb[(size_t)sA * 64 + sub * 4];
        uint4 pB = *(const uint4*)&g_hpb[(size_t)sB * 64 + sub * 4];
        den += eA + eB;
        u64 eAp = pkf(eA, eA);
        u64 eBp = pkf(eB, eB);
        pfma(acc[0], eAp, bfexpand(pA.x));
        pfma(acc[1], eAp, bfexpand(pA.y));
        pfma(acc[2], eAp, bfexpand(pA.z));
        pfma(acc[3], eAp, bfexpand(pA.w));
        pfma(acc[0], eBp, bfexpand(pB.x));
        pfma(acc[1], eBp, bfexpand(pB.y));
        pfma(acc[2], eBp, bfexpand(pB.z));
        pfma(acc[3], eBp, bfexpand(pB.w));
    }
    for (; i + 2 <= end; i += 2) {
        int sA = g_csr_src[i + pairlane];
        float lA = g_alS[sA * 4 + head] + adh;
        lA = (lA > 0.f) ? lA : 0.2f * lA;
        float eA = __expf(lA);
        uint4 pA = *(const uint4*)&g_hpb[(size_t)sA * 64 + sub * 4];
        den += eA;
        u64 eAp = pkf(eA, eA);
        pfma(acc[0], eAp, bfexpand(pA.x));
        pfma(acc[1], eAp, bfexpand(pA.y));
        pfma(acc[2], eAp, bfexpand(pA.z));
        pfma(acc[3], eAp, bfexpand(pA.w));
    }
    if (i < end) {
        int sA = g_csr_src[i];
        float lA = g_alS[sA * 4 + head] + adh;
        lA = (lA > 0.f) ? lA : 0.2f * lA;
        float eA = (pairlane == 0) ? __expf(lA) : 0.f;
        uint4 pA = *(const uint4*)&g_hpb[(size_t)sA * 64 + sub * 4];
        den += eA;
        u64 eAp = pkf(eA, eA);
        pfma(acc[0], eAp, bfexpand(pA.x));
        pfma(acc[1], eAp, bfexpand(pA.y));
        pfma(acc[2], eAp, bfexpand(pA.z));
        pfma(acc[3], eAp, bfexpand(pA.w));
    }

    float a[8];
#pragma unroll
    for (int k = 0; k < 4; k++) { a[2 * k] = lo32(acc[k]); a[2 * k + 1] = hi32(acc[k]); }

    den += __shfl_xor_sync(0xffffffffu, den, 16);
#pragma unroll
    for (int k = 0; k < 8; k++) a[k] += __shfl_xor_sync(0xffffffffu, a[k], 16);

    float dinv = 1.0f / (den + 1e-16f);

    int d0 = sub * 8;
    size_t base = (size_t)n * Hq + d0;
    float4 h0 = *(const float4*)&g_h[base];
    float4 h1 = *(const float4*)&g_h[base + 4];
    float4 b0 = *(const float4*)&bg[d0];
    float4 b1 = *(const float4*)&bg[d0 + 4];
    float v[8];
    v[0] = a[0] * dinv + b0.x + h0.x;
    v[1] = a[1] * dinv + b0.y + h0.y;
    v[2] = a[2] * dinv + b0.z + h0.z;
    v[3] = a[3] * dinv + b0.w + h0.w;
    v[4] = a[4] * dinv + b1.x + h1.x;
    v[5] = a[5] * dinv + b1.y + h1.y;
    v[6] = a[6] * dinv + b1.z + h1.z;
    v[7] = a[7] * dinv + b1.w + h1.w;

    float s = 0.f, t = 0.f;
#pragma unroll
    for (int k = 0; k < 8; k++) { s += v[k]; t += v[k] * v[k]; }
#pragma unroll
    for (int o = 8; o; o >>= 1) {
        s += __shfl_xor_sync(0xffffffffu, s, o);
        t += __shfl_xor_sync(0xffffffffu, t, o);
    }
    float mu = s * (1.0f / 128.0f);
    float var = t * (1.0f / 128.0f) - mu * mu;
    float rs = rsqrtf(var + 1e-5f);

    if (pairlane == 0) {
        float4 g0 = *(const float4*)&ga[d0];
        float4 g1 = *(const float4*)&ga[d0 + 4];
        float4 e0 = *(const float4*)&be[d0];
        float4 e1 = *(const float4*)&be[d0 + 4];
        float4 o0, o1;
        o0.x = (v[0] - mu) * rs * g0.x + e0.x;
        o0.y = (v[1] - mu) * rs * g0.y + e0.y;
        o0.z = (v[2] - mu) * rs * g0.z + e0.z;
        o0.w = (v[3] - mu) * rs * g0.w + e0.w;
        o1.x = (v[4] - mu) * rs * g1.x + e1.x;
        o1.y = (v[5] - mu) * rs * g1.y + e1.y;
        o1.z = (v[6] - mu) * rs * g1.z + e1.z;
        o1.w = (v[7] - mu) * rs * g1.w + e1.w;
        *(float4*)&g_h[base] = o0;
        *(float4*)&g_h[base + 4] = o1;
    }
}

// ---------------- pooling ----------------
__global__ void pool_clear()
{
    int idx = blockIdx.x * blockDim.x + threadIdx.x;
    if (idx < Gq * Hq) { g_psum[idx] = 0.f; g_pmax[idx] = -INFINITY; }
    if (idx < Gq) g_gcnt[idx] = 0.f;
}

__global__ void pool_chunk(const int* __restrict__ n2g)
{
    __shared__ int sg[256];
    int d  = threadIdx.x;
    int n0 = blockIdx.x * 256;
    int n1 = n0 + 256; if (n1 > Nn) n1 = Nn;
    int cn = n1 - n0;
    for (int i = d; i < cn; i += 128) sg[i] = n2g[n0 + i];
    __syncthreads();

    int   curg = sg[0];
    float sum = 0.f, mx = -INFINITY;
    int   cnt = 0;
    for (int j = 0; j < cn; j++) {
        int g = sg[j];
        if (g != curg) {
            atomicAdd(&g_psum[curg * Hq + d], sum);
            atomicMaxFloat(&g_pmax[curg * Hq + d], mx);
            if (d == 0) atomicAdd(&g_gcnt[curg], (float)cnt);
            sum = 0.f; mx = -INFINITY; cnt = 0; curg = g;
        }
        float v = g_h[(size_t)(n0 + j) * Hq + d];
        sum += v; mx = fmaxf(mx, v); cnt++;
    }
    atomicAdd(&g_psum[curg * Hq + d], sum);
    atomicMaxFloat(&g_pmax[curg * Hq + d], mx);
    if (d == 0) atomicAdd(&g_gcnt[curg], (float)cnt);
}

// ---------------- final MLP head ----------------
__global__ void final_mlp(const float* __restrict__ Wq1, const float* __restrict__ bq1,
                          const float* __restrict__ gq, const float* __restrict__ beq,
                          const float* __restrict__ Wq2, const float* __restrict__ bq2,
                          float* __restrict__ out)
{
    int g = blockIdx.x;
    int tid = threadIdx.x;   // 256
    __shared__ float emb[2 * Hq];
    __shared__ float p[Hq];
    __shared__ float stats[2];

    if (tid < Hq) emb[tid] = g_psum[g * Hq + tid] / fmaxf(g_gcnt[g], 1.0f);
    else          emb[tid] = g_pmax[g * Hq + (tid - Hq)];
    __syncthreads();

    if (tid < Hq) {
        float t = bq1[tid];
        for (int k = 0; k < 2 * Hq; k++) t += emb[k] * Wq1[k * Hq + tid];
        p[tid] = t;
    }
    __syncthreads();

    if (tid == 0) {
        float s = 0.f;
        for (int j = 0; j < Hq; j++) s += p[j];
        float mu = s * (1.0f / 128.0f);
        float v = 0.f;
        for (int j = 0; j < Hq; j++) { float dd = p[j] - mu; v += dd * dd; }
        stats[0] = mu;
        stats[1] = rsqrtf(v * (1.0f / 128.0f) + 1e-5f);
    }
    __syncthreads();

    if (tid < Hq) {
        float y = (p[tid] - stats[0]) * stats[1] * gq[tid] + beq[tid];
        p[tid] = gelu_exact(y);
    }
    __syncthreads();

    float o = bq2[tid];
    for (int k = 0; k < Hq; k++) o += p[k] * Wq2[k * FOUTq + tid];
    out[g * FOUTq + tid] = o;
}

// ---------------- launch ----------------
extern "C" void kernel_launch(void* const* d_in, const int* in_sizes, int n_in,
                              void* d_out, int out_size)
{
    const float* x   = (const float*)d_in[0];
    const int*   ei  = (const int*)d_in[1];
    const int*   n2g = (const int*)d_in[2];
    const float* Wp  = (const float*)d_in[3];
    const float* bp  = (const float*)d_in[4];
    const float* Wq1 = (const float*)d_in[5];
    const float* bq1 = (const float*)d_in[6];
    const float* gq  = (const float*)d_in[7];
    const float* beq = (const float*)d_in[8];
    const float* Wq2 = (const float*)d_in[9];
    const float* bq2 = (const float*)d_in[10];
    float* out = (float*)d_out;

    float* ph = nullptr;
    void* pcnt = nullptr;
    cudaGetSymbolAddress((void**)&ph, g_h);
    cudaGetSymbolAddress(&pcnt, g_cnt_i);

    static cudaStream_t s2 = nullptr;
    static cudaEvent_t evA = nullptr, evB = nullptr, evC = nullptr;
    if (s2 == nullptr) {
        cudaStreamCreateWithFlags(&s2, cudaStreamNonBlocking);
        cudaEventCreateWithFlags(&evA, cudaEventDisableTiming);
        cudaEventCreateWithFlags(&evB, cudaEventDisableTiming);
        cudaEventCreateWithFlags(&evC, cudaEventDisableTiming);
    }

    const int NB_GEMM = (Nn + 127) / 128;
    const int NB_E    = (ETOT + 255) / 256;
    const int NB_AGG  = Nn / 8;
    const int NB_POOL = (Nn + 255) / 256;

    // ---- side stream: CSR build (overlaps with proj + layer-0 GEMM) ----
    cudaEventRecord(evA, 0);
    cudaStreamWaitEvent(s2, evA, 0);
    cudaMemsetAsync(pcnt, 0, Nn * sizeof(int), s2);

    gemm_proj<<<NB_GEMM, 256>>>(x, Wp, bp, ph, Nn);              // kernel 1
    hist_dst<<<NB_E, 256, 0, s2>>>(ei);                          // kernel 2
    scan_dl<<<NTILE, 256, 0, s2>>>();                            // kernel 3
    gemm_bf16<<<NB_GEMM, 256>>>(ph, (const float*)d_in[11],
                                (const float*)d_in[12], (const float*)d_in[13], Nn); // kernel 4 (PROFILED)
    csr_fill<<<NB_E, 256, 0, s2>>>(ei);                          // kernel 5
    cudaEventRecord(evB, s2);

    cudaStreamWaitEvent(0, evB, 0);
    gat_agg_ln<<<NB_AGG, 256>>>((const float*)d_in[14], (const float*)d_in[15],
                                (const float*)d_in[16]);

    gemm_bf16<<<NB_GEMM, 256>>>(ph, (const float*)d_in[17],
                                (const float*)d_in[18], (const float*)d_in[19], Nn);
    gat_agg_ln<<<NB_AGG, 256>>>((const float*)d_in[20], (const float*)d_in[21],
                                (const float*)d_in[22]);

    pool_clear<<<(Gq * Hq + 255) / 256, 256, 0, s2>>>();
    cudaEventRecord(evC, s2);
    cudaStreamWaitEvent(0, evC, 0);
    pool_chunk<<<NB_POOL, 128>>>(n2g);
    final_mlp<<<Gq, 256>>>(Wq1, bq1, gq, beq, Wq2, bq2, out);
}

// round 15
// speedup vs baseline: 1.1893x; 1.0002x over previous
#include <cuda_runtime.h>
#include <cuda_bf16.h>
#include <math.h>

#define Nn   100000
#define Ee   1600000
#define ETOT (Ee + Nn)
#define DINq 16
#define Hq   128
#define HEADSq 4
#define Gq   64
#define FOUTq 256
#define NTILE ((Nn + 255) / 256)

typedef unsigned long long u64;
typedef unsigned int u32;

// ---- scratch (static device memory) ----
__device__ float g_h[(size_t)Nn * Hq];
__device__ u32   g_hb[(size_t)Nn * (Hq / 2)];    // bf16x2 copy of h (GEMM A input)
__device__ u32   g_hpb[(size_t)Nn * (Hq / 2)];   // bf16x2 h@Wg
__device__ u32   g_Wb[2 * 8192];                 // pre-packed layer weights
__device__ float g_alS[Nn * HEADSq];
__device__ float g_alD[Nn * HEADSq];
__device__ int   g_cnt_i[Nn];
__device__ int   g_rowptr[Nn + 1];
__device__ int   g_cursor[Nn];
__device__ int   g_csr_src[ETOT];
__device__ u64   g_tstat[NTILE];
__device__ float g_psum[Gq * Hq];
__device__ float g_pmax[Gq * Hq];
__device__ float g_gcnt[Gq];

#define FLAG_AGG (1ull << 62)
#define FLAG_INC (1ull << 63)

__device__ __forceinline__ void atomicMaxFloat(float* addr, float v) {
    if (v >= 0.0f) atomicMax((int*)addr, __float_as_int(v));
    else           atomicMin((unsigned int*)addr, __float_as_uint(v));
}

__device__ __forceinline__ float gelu_exact(float v) {
    return 0.5f * v * (1.0f + erff(v * 0.70710678118654752f));
}

__device__ __forceinline__ u32 bfpack(float lo, float hi) {
    u32 r; asm("cvt.rn.bf16x2.f32 %0, %1, %2;" : "=r"(r) : "f"(hi), "f"(lo)); return r;
}

__device__ __forceinline__ void mma_bf16(float* c, const u32* a, u32 b0, u32 b1) {
    asm volatile("mma.sync.aligned.m16n8k16.row.col.f32.bf16.bf16.f32 "
        "{%0,%1,%2,%3}, {%4,%5,%6,%7}, {%8,%9}, {%0,%1,%2,%3};"
        : "+f"(c[0]), "+f"(c[1]), "+f"(c[2]), "+f"(c[3])
        : "r"(a[0]), "r"(a[1]), "r"(a[2]), "r"(a[3]), "r"(b0), "r"(b1));
}

// ---- packed f32x2 helpers ----
__device__ __forceinline__ void pfma(u64& d, u64 a, u64 b) {
    asm("fma.rn.f32x2 %0, %1, %2, %0;" : "+l"(d) : "l"(a), "l"(b));
}
__device__ __forceinline__ u64 pku(u32 lo, u32 hi) {
    u64 r; asm("mov.b64 %0, {%1,%2};" : "=l"(r) : "r"(lo), "r"(hi)); return r;
}
__device__ __forceinline__ u64 pkf(float lo, float hi) {
    u64 r; asm("mov.b64 %0, {%1,%2};" : "=l"(r) : "f"(lo), "f"(hi)); return r;
}
__device__ __forceinline__ u64 swap64(u64 p) { return pku((u32)(p >> 32), (u32)p); }
__device__ __forceinline__ float lo32(u64 p) { return __uint_as_float((u32)p); }
__device__ __forceinline__ float hi32(u64 p) { return __uint_as_float((u32)(p >> 32)); }
__device__ __forceinline__ u64 bfexpand(u32 w) {
    return pku(w << 16, w & 0xffff0000u);
}

// ------- weight pre-pack: W[k][n] fp32 -> Wu word layout [chunk][kp][n] -------
__global__ void w_convert(const float* __restrict__ W0, const float* __restrict__ W1)
{
    int i = blockIdx.x * 256 + threadIdx.x;
    if (i >= 2 * 8192) return;
    const float* W = (i < 8192) ? W0 : W1;
    int wi = i & 8191;
    int cc = wi >> 11;             // 32-k chunk
    int kp = (wi >> 7) & 15;       // word row within chunk
    int n  = wi & 127;
    int k  = cc * 32 + 2 * kp;
    g_Wb[i] = bfpack(W[k * Hq + n], W[(k + 1) * Hq + n]);
}

// ------- proj GEMM (K=16): h = gelu(x @ Wp + bp), FFMA2; writes fp32 + bf16 -------
__global__ void gemm_proj(const float* __restrict__ A, const float* __restrict__ W,
                          const float* __restrict__ bias, float* __restrict__ C, int M)
{
    const int BN = 128, BK = 16;
    __shared__ float As[BK][BN + 4];
    __shared__ float Ws[BK][Hq + 4];
    int tid = threadIdx.x;
    int tx = tid & 15, ty = tid >> 4;
    int m0 = blockIdx.x * BN;
    int c0 = tx * 8;
    int r0 = ty * 8;

    u64 acc[4][4][2];
#pragma unroll
    for (int rp = 0; rp < 4; rp++)
#pragma unroll
        for (int cp = 0; cp < 4; cp++) { acc[rp][cp][0] = 0ull; acc[rp][cp][1] = 0ull; }

#pragma unroll
    for (int i = tid; i < BN * BK; i += 256) {
        int r = i >> 4, k = i & 15;
        As[k][r] = (m0 + r < M) ? A[(size_t)(m0 + r) * DINq + k] : 0.f;
    }
#pragma unroll
    for (int i = tid; i < BK * Hq; i += 256) {
        int k = i >> 7, c = i & 127;
        Ws[k][c] = W[(size_t)k * Hq + c];
    }
    __syncthreads();
#pragma unroll
    for (int kk = 0; kk < BK; kk++) {
        ulonglong2 ra = *(const ulonglong2*)&As[kk][r0];
        ulonglong2 rb = *(const ulonglong2*)&As[kk][r0 + 4];
        ulonglong2 wa = *(const ulonglong2*)&Ws[kk][c0];
        ulonglong2 wb = *(const ulonglong2*)&Ws[kk][c0 + 4];
        u64 rr[4] = {ra.x, ra.y, rb.x, rb.y};
        u64 cn[4] = {wa.x, wa.y, wb.x, wb.y};
        u64 cs[4] = {swap64(wa.x), swap64(wa.y), swap64(wb.x), swap64(wb.y)};
#pragma unroll
        for (int rp = 0; rp < 4; rp++)
#pragma unroll
            for (int cp = 0; cp < 4; cp++) {
                pfma(acc[rp][cp][0], rr[rp], cn[cp]);
                pfma(acc[rp][cp][1], rr[rp], cs[cp]);
            }
    }

    float v[8][8];
#pragma unroll
    for (int rp = 0; rp < 4; rp++)
#pragma unroll
        for (int cp = 0; cp < 4; cp++) {
            v[2 * rp][2 * cp]         = lo32(acc[rp][cp][0]);
            v[2 * rp + 1][2 * cp + 1] = hi32(acc[rp][cp][0]);
            v[2 * rp][2 * cp + 1]     = lo32(acc[rp][cp][1]);
            v[2 * rp + 1][2 * cp]     = hi32(acc[rp][cp][1]);
        }

    float b8[8];
#pragma unroll
    for (int q = 0; q < 8; q++) b8[q] = bias[c0 + q];
#pragma unroll
    for (int r = 0; r < 8; r++) {
        int m = m0 + r0 + r;
        if (m < M) {
#pragma unroll
            for (int q = 0; q < 8; q++) v[r][q] = gelu_exact(v[r][q] + b8[q]);
            float4 o0 = make_float4(v[r][0], v[r][1], v[r][2], v[r][3]);
            float4 o1 = make_float4(v[r][4], v[r][5], v[r][6], v[r][7]);
            *(float4*)&C[(size_t)m * Hq + c0] = o0;
            *(float4*)&C[(size_t)m * Hq + c0 + 4] = o1;
            uint4 ob;
            ob.x = bfpack(v[r][0], v[r][1]);
            ob.y = bfpack(v[r][2], v[r][3]);
            ob.z = bfpack(v[r][4], v[r][5]);
            ob.w = bfpack(v[r][6], v[r][7]);
            *(uint4*)&g_hb[(size_t)m * 64 + tx * 4] = ob;
        }
    }
}

// ------- layer GEMM: bf16 MMA, pre-packed operands, A resident, W double-buffered -------
__global__ void __launch_bounds__(256, 2) gemm_bf16(
    const u32* __restrict__ Ab, const u32* __restrict__ Wb,
    const float* __restrict__ a_s, const float* __restrict__ a_d, int M)
{
    extern __shared__ u32 dyn[];
    u32* Au = dyn;                    // [128][68]
    u32* Wu = dyn + 128 * 68;         // [2][16][132]
    int tid = threadIdx.x;
    int w = tid >> 5, lane = tid & 31;
    int wr = w >> 1, wc = w & 1;
    int q = lane & 3, g = lane >> 2;
    int m0 = blockIdx.x * 128;

    float c[2][8][4];
#pragma unroll
    for (int mt = 0; mt < 2; mt++)
#pragma unroll
        for (int nt = 0; nt < 8; nt++)
#pragma unroll
            for (int f = 0; f < 4; f++) c[mt][nt][f] = 0.f;

    // ---- whole A tile: 128 rows x 64 words, direct bf16 load ----
#pragma unroll
    for (int it = 0; it < 8; it++) {
        int widx4 = it * 256 + tid;
        int wd = widx4 * 4;
        int r = wd >> 6, cI = wd & 63;
        uint4 v = make_uint4(0u, 0u, 0u, 0u);
        if (m0 + r < M) v = *(const uint4*)&Ab[(size_t)(m0 + r) * 64 + cI];
        *(uint4*)&Au[r * 68 + cI] = v;
    }
    // ---- W chunk 0 ----
    int wkp = tid >> 4, wnI = (tid * 8) & 127;
    uint4 wA = *(const uint4*)&Wb[tid * 8];
    uint4 wB = *(const uint4*)&Wb[tid * 8 + 4];
    *(uint4*)&Wu[wkp * 132 + wnI]     = wA;
    *(uint4*)&Wu[wkp * 132 + wnI + 4] = wB;
    __syncthreads();

    for (int cc = 0; cc < 4; cc++) {
        if (cc < 3) {
            wA = *(const uint4*)&Wb[(cc + 1) * 2048 + tid * 8];
            wB = *(const uint4*)&Wb[(cc + 1) * 2048 + tid * 8 + 4];
        }
        int bufo = (cc & 1) * 2112;
#pragma unroll
        for (int kh = 0; kh < 2; kh++) {
            int ks = cc * 2 + kh;
            int kpA = ks * 8 + q;
            int kpW = kh * 8 + q;
            u32 af[2][4];
#pragma unroll
            for (int mt = 0; mt < 2; mt++) {
                int r = wr * 32 + mt * 16;
                af[mt][0] = Au[(r + g) * 68 + kpA];
                af[mt][1] = Au[(r + g + 8) * 68 + kpA];
                af[mt][2] = Au[(r + g) * 68 + kpA + 4];
                af[mt][3] = Au[(r + g + 8) * 68 + kpA + 4];
            }
#pragma unroll
            for (int nt = 0; nt < 8; nt++) {
                int n = wc * 64 + nt * 8 + g;
                u32 b0 = Wu[bufo + kpW * 132 + n];
                u32 b1 = Wu[bufo + (kpW + 4) * 132 + n];
                mma_bf16(c[0][nt], af[0], b0, b1);
                mma_bf16(c[1][nt], af[1], b0, b1);
            }
        }
        if (cc < 3) {
            int b2 = ((cc + 1) & 1) * 2112;
            *(uint4*)&Wu[b2 + wkp * 132 + wnI]     = wA;
            *(uint4*)&Wu[b2 + wkp * 132 + wnI + 4] = wB;
        }
        __syncthreads();
    }

    // epilogue 1: bf16 pack of hp
#pragma unroll
    for (int mt = 0; mt < 2; mt++)
#pragma unroll
        for (int half = 0; half < 2; half++) {
            int m = m0 + wr * 32 + mt * 16 + g + half * 8;
            if (m < M) {
#pragma unroll
                for (int nt = 0; nt < 8; nt++) {
                    u32 pw = bfpack(c[mt][nt][2 * half], c[mt][nt][2 * half + 1]);
                    g_hpb[(size_t)m * (Hq / 2) + wc * 32 + nt * 4 + q] = pw;
                }
            }
        }

    // epilogue 2: attn logits (2 heads per warp)
    float asv[8][2], adv[8][2];
#pragma unroll
    for (int nt = 0; nt < 8; nt++) {
        int col = wc * 64 + nt * 8 + 2 * q;
        asv[nt][0] = a_s[col];     asv[nt][1] = a_s[col + 1];
        adv[nt][0] = a_d[col];     adv[nt][1] = a_d[col + 1];
    }
#pragma unroll
    for (int mt = 0; mt < 2; mt++)
#pragma unroll
        for (int half = 0; half < 2; half++) {
            int m = m0 + wr * 32 + mt * 16 + g + half * 8;
            float ps0 = 0.f, ps1 = 0.f, pd0 = 0.f, pd1 = 0.f;
#pragma unroll
            for (int nt = 0; nt < 8; nt++) {
                float x0 = c[mt][nt][2 * half], x1 = c[mt][nt][2 * half + 1];
                float s = x0 * asv[nt][0] + x1 * asv[nt][1];
                float d = x0 * adv[nt][0] + x1 * adv[nt][1];
                if (nt < 4) { ps0 += s; pd0 += d; }
                else        { ps1 += s; pd1 += d; }
            }
            ps0 += __shfl_xor_sync(0xffffffffu, ps0, 1);
            ps1 += __shfl_xor_sync(0xffffffffu, ps1, 1);
            pd0 += __shfl_xor_sync(0xffffffffu, pd0, 1);
            pd1 += __shfl_xor_sync(0xffffffffu, pd1, 1);
            ps0 += __shfl_xor_sync(0xffffffffu, ps0, 2);
            ps1 += __shfl_xor_sync(0xffffffffu, ps1, 2);
            pd0 += __shfl_xor_sync(0xffffffffu, pd0, 2);
            pd1 += __shfl_xor_sync(0xffffffffu, pd1, 2);
            if (q == 0 && m < M) {
                int hb = wc * 2;
                g_alS[m * 4 + hb]     = ps0;
                g_alS[m * 4 + hb + 1] = ps1;
                g_alD[m * 4 + hb]     = pd0;
                g_alD[m * 4 + hb + 1] = pd1;
            }
        }
}

// ================= CSR build =================
__global__ void hist_dst(const int* __restrict__ ei)
{
    int e = blockIdx.x * blockDim.x + threadIdx.x;
    if (e < NTILE) g_tstat[e] = 0;
    if (e >= ETOT) return;
    int d = (e < Ee) ? ei[Ee + e] : (e - Ee);
    atomicAdd(&g_cnt_i[d], 1);
}

__global__ void scan_dl()
{
    __shared__ int s[256];
    __shared__ int s_prefix;
    int bid = blockIdx.x, tid = threadIdx.x;
    int i = bid * 256 + tid;
    int v = (i < Nn) ? g_cnt_i[i] : 0;
    s[tid] = v;
    __syncthreads();
#pragma unroll
    for (int o = 1; o < 256; o <<= 1) {
        int t = (tid >= o) ? s[tid - o] : 0;
        __syncthreads();
        s[tid] += t;
        __syncthreads();
    }
    int incl = s[tid];
    int agg  = s[255];

    if (tid == 0) {
        u64 pub = (bid == 0) ? (FLAG_INC | (u64)(u32)agg) : (FLAG_AGG | (u64)(u32)agg);
        atomicExch((unsigned long long*)&g_tstat[bid], pub);
        if (bid == 0) s_prefix = 0;
    }

    if (bid > 0 && tid < 32) {
        int lane = tid;
        u32 running = 0;
        int look = bid - 1;
        while (true) {
            int t = look - lane;
            u64 st;
            if (t >= 0) {
                do { st = *(volatile u64*)&g_tstat[t]; } while (st == 0);
            } else {
                st = FLAG_INC;
            }
            u32 incm = __ballot_sync(0xffffffffu, (st & FLAG_INC) != 0);
            u32 val;
            if (incm) {
                int L = __ffs(incm) - 1;
                val = (lane <= L) ? (u32)st : 0;
            } else {
                val = (u32)st;
            }
#pragma unroll
            for (int o = 16; o; o >>= 1) val += __shfl_xor_sync(0xffffffffu, val, o);
            running += val;
            if (incm) break;
            look -= 32;
        }
        if (lane == 0) {
            atomicExch((unsigned long long*)&g_tstat[bid],
                       FLAG_INC | (u64)(u32)(running + (u32)agg));
            s_prefix = (int)running;
        }
    }
    __syncthreads();

    int pre = s_prefix;
    if (i < Nn) {
        int r = pre + incl - v;
        g_rowptr[i] = r;
        g_cursor[i] = r;
    }
    if (i == 0) g_rowptr[Nn] = ETOT;
}

__global__ void csr_fill(const int* __restrict__ ei)
{
    int e = blockIdx.x * blockDim.x + threadIdx.x;
    if (e >= ETOT) return;
    int s, d;
    if (e < Ee) { s = ei[e]; d = ei[Ee + e]; } else { s = d = e - Ee; }
    int pos = atomicAdd(&g_cursor[d], 1);
    g_csr_src[pos] = s;
}

// == GAT aggregation: warp per node, half-warp per edge, packed f32x2 FMA ==
__global__ void gat_agg_ln(const float* __restrict__ bg, const float* __restrict__ ga,
                           const float* __restrict__ be, int whb)
{
    int n = blockIdx.x * 8 + (threadIdx.x >> 5);
    if (n >= Nn) return;
    int lane = threadIdx.x & 31;
    int pairlane = lane >> 4;
    int sub = lane & 15;
    int head = sub >> 2;

    int start = g_rowptr[n];
    int end   = g_rowptr[n + 1];
    float adh = g_alD[n * 4 + head];

    u64 acc[4];
#pragma unroll
    for (int k = 0; k < 4; k++) acc[k] = 0ull;
    float den = 0.f;

    int i = start;
    for (; i + 4 <= end; i += 4) {
        int sA = g_csr_src[i + pairlane];
        int sB = g_csr_src[i + 2 + pairlane];
        float lA = g_alS[sA * 4 + head] + adh;
        float lB = g_alS[sB * 4 + head] + adh;
        lA = (lA > 0.f) ? lA : 0.2f * lA;
        lB = (lB > 0.f) ? lB : 0.2f * lB;
        float eA = __expf(lA);
        float eB = __expf(lB);
        uint4 pA = *(const uint4*)&g_hpb[(size_t)sA * 64 + sub * 4];
        uint4 pB = *(const uint4*)&g_hpb[(size_t)sB * 64 + sub * 4];
        den += eA + eB;
        u64 eAp = pkf(eA, eA);
        u64 eBp = pkf(eB, eB);
        pfma(acc[0], eAp, bfexpand(pA.x));
        pfma(acc[1], eAp, bfexpand(pA.y));
        pfma(acc[2], eAp, bfexpand(pA.z));
        pfma(acc[3], eAp, bfexpand(pA.w));
        pfma(acc[0], eBp, bfexpand(pB.x));
        pfma(acc[1], eBp, bfexpand(pB.y));
        pfma(acc[2], eBp, bfexpand(pB.z));
        pfma(acc[3], eBp, bfexpand(pB.w));
    }
    for (; i + 2 <= end; i += 2) {
        int sA = g_csr_src[i + pairlane];
        float lA = g_alS[sA * 4 + head] + adh;
        lA = (lA > 0.f) ? lA : 0.2f * lA;
        float eA = __expf(lA);
        uint4 pA = *(const uint4*)&g_hpb[(size_t)sA * 64 + sub * 4];
        den += eA;
        u64 eAp = pkf(eA, eA);
        pfma(acc[0], eAp, bfexpand(pA.x));
        pfma(acc[1], eAp, bfexpand(pA.y));
        pfma(acc[2], eAp, bfexpand(pA.z));
        pfma(acc[3], eAp, bfexpand(pA.w));
    }
    if (i < end) {
        int sA = g_csr_src[i];
        float lA = g_alS[sA * 4 + head] + adh;
        lA = (lA > 0.f) ? lA : 0.2f * lA;
        float eA = (pairlane == 0) ? __expf(lA) : 0.f;
        uint4 pA = *(const uint4*)&g_hpb[(size_t)sA * 64 + sub * 4];
        den += eA;
        u64 eAp = pkf(eA, eA);
        pfma(acc[0], eAp, bfexpand(pA.x));
        pfma(acc[1], eAp, bfexpand(pA.y));
        pfma(acc[2], eAp, bfexpand(pA.z));
        pfma(acc[3], eAp, bfexpand(pA.w));
    }

    float a[8];
#pragma unroll
    for (int k = 0; k < 4; k++) { a[2 * k] = lo32(acc[k]); a[2 * k + 1] = hi32(acc[k]); }

    den += __shfl_xor_sync(0xffffffffu, den, 16);
#pragma unroll
    for (int k = 0; k < 8; k++) a[k] += __shfl_xor_sync(0xffffffffu, a[k], 16);

    float dinv = 1.0f / (den + 1e-16f);

    int d0 = sub * 8;
    size_t base = (size_t)n * Hq + d0;
    float4 h0 = *(const float4*)&g_h[base];
    float4 h1 = *(const float4*)&g_h[base + 4];
    float4 b0 = *(const float4*)&bg[d0];
    float4 b1 = *(const float4*)&bg[d0 + 4];
    float v[8];
    v[0] = a[0] * dinv + b0.x + h0.x;
    v[1] = a[1] * dinv + b0.y + h0.y;
    v[2] = a[2] * dinv + b0.z + h0.z;
    v[3] = a[3] * dinv + b0.w + h0.w;
    v[4] = a[4] * dinv + b1.x + h1.x;
    v[5] = a[5] * dinv + b1.y + h1.y;
    v[6] = a[6] * dinv + b1.z + h1.z;
    v[7] = a[7] * dinv + b1.w + h1.w;

    float s = 0.f, t = 0.f;
#pragma unroll
    for (int k = 0; k < 8; k++) { s += v[k]; t += v[k] * v[k]; }
#pragma unroll
    for (int o = 8; o; o >>= 1) {
        s += __shfl_xor_sync(0xffffffffu, s, o);
        t += __shfl_xor_sync(0xffffffffu, t, o);
    }
    float mu = s * (1.0f / 128.0f);
    float var = t * (1.0f / 128.0f) - mu * mu;
    float rs = rsqrtf(var + 1e-5f);

    if (pairlane == 0) {
        float4 g0 = *(const float4*)&ga[d0];
        float4 g1 = *(const float4*)&ga[d0 + 4];
        float4 e0 = *(const float4*)&be[d0];
        float4 e1 = *(const float4*)&be[d0 + 4];
        float4 o0, o1;
        o0.x = (v[0] - mu) * rs * g0.x + e0.x;
        o0.y = (v[1] - mu) * rs * g0.y + e0.y;
        o0.z = (v[2] - mu) * rs * g0.z + e0.z;
        o0.w = (v[3] - mu) * rs * g0.w + e0.w;
        o1.x = (v[4] - mu) * rs * g1.x + e1.x;
        o1.y = (v[5] - mu) * rs * g1.y + e1.y;
        o1.z = (v[6] - mu) * rs * g1.z + e1.z;
        o1.w = (v[7] - mu) * rs * g1.w + e1.w;
        *(float4*)&g_h[base] = o0;
        *(float4*)&g_h[base + 4] = o1;
        if (whb) {
            uint4 ob;
            ob.x = bfpack(o0.x, o0.y);
            ob.y = bfpack(o0.z, o0.w);
            ob.z = bfpack(o1.x, o1.y);
            ob.w = bfpack(o1.z, o1.w);
            *(uint4*)&g_hb[(size_t)n * 64 + sub * 4] = ob;
        }
    }
}

// ---------------- pooling ----------------
__global__ void pool_clear()
{
    int idx = blockIdx.x * blockDim.x + threadIdx.x;
    if (idx < Gq * Hq) { g_psum[idx] = 0.f; g_pmax[idx] = -INFINITY; }
    if (idx < Gq) g_gcnt[idx] = 0.f;
}

__global__ void pool_chunk(const int* __restrict__ n2g)
{
    __shared__ int sg[256];
    int d  = threadIdx.x;
    int n0 = blockIdx.x * 256;
    int n1 = n0 + 256; if (n1 > Nn) n1 = Nn;
    int cn = n1 - n0;
    for (int i = d; i < cn; i += 128) sg[i] = n2g[n0 + i];
    __syncthreads();

    int   curg = sg[0];
    float sum = 0.f, mx = -INFINITY;
    int   cnt = 0;
    for (int j = 0; j < cn; j++) {
        int g = sg[j];
        if (g != curg) {
            atomicAdd(&g_psum[curg * Hq + d], sum);
            atomicMaxFloat(&g_pmax[curg * Hq + d], mx);
            if (d == 0) atomicAdd(&g_gcnt[curg], (float)cnt);
            sum = 0.f; mx = -INFINITY; cnt = 0; curg = g;
        }
        float v = g_h[(size_t)(n0 + j) * Hq + d];
        sum += v; mx = fmaxf(mx, v); cnt++;
    }
    atomicAdd(&g_psum[curg * Hq + d], sum);
    atomicMaxFloat(&g_pmax[curg * Hq + d], mx);
    if (d == 0) atomicAdd(&g_gcnt[curg], (float)cnt);
}

// ---------------- final MLP head ----------------
__global__ void final_mlp(const float* __restrict__ Wq1, const float* __restrict__ bq1,
                          const float* __restrict__ gq, const float* __restrict__ beq,
                          const float* __restrict__ Wq2, const float* __restrict__ bq2,
                          float* __restrict__ out)
{
    int g = blockIdx.x;
    int tid = threadIdx.x;   // 256
    __shared__ float emb[2 * Hq];
    __shared__ float p[Hq];
    __shared__ float stats[2];

    if (tid < Hq) emb[tid] = g_psum[g * Hq + tid] / fmaxf(g_gcnt[g], 1.0f);
    else          emb[tid] = g_pmax[g * Hq + (tid - Hq)];
    __syncthreads();

    if (tid < Hq) {
        float t = bq1[tid];
        for (int k = 0; k < 2 * Hq; k++) t += emb[k] * Wq1[k * Hq + tid];
        p[tid] = t;
    }
    __syncthreads();

    if (tid == 0) {
        float s = 0.f;
        for (int j = 0; j < Hq; j++) s += p[j];
        float mu = s * (1.0f / 128.0f);
        float v = 0.f;
        for (int j = 0; j < Hq; j++) { float dd = p[j] - mu; v += dd * dd; }
        stats[0] = mu;
        stats[1] = rsqrtf(v * (1.0f / 128.0f) + 1e-5f);
    }
    __syncthreads();

    if (tid < Hq) {
        float y = (p[tid] - stats[0]) * stats[1] * gq[tid] + beq[tid];
        p[tid] = gelu_exact(y);
    }
    __syncthreads();

    float o = bq2[tid];
    for (int k = 0; k < Hq; k++) o += p[k] * Wq2[k * FOUTq + tid];
    out[g * FOUTq + tid] = o;
}

// ---------------- launch ----------------
extern "C" void kernel_launch(void* const* d_in, const int* in_sizes, int n_in,
                              void* d_out, int out_size)
{
    const float* x   = (const float*)d_in[0];
    const int*   ei  = (const int*)d_in[1];
    const int*   n2g = (const int*)d_in[2];
    const float* Wp  = (const float*)d_in[3];
    const float* bp  = (const float*)d_in[4];
    const float* Wq1 = (const float*)d_in[5];
    const float* bq1 = (const float*)d_in[6];
    const float* gq  = (const float*)d_in[7];
    const float* beq = (const float*)d_in[8];
    const float* Wq2 = (const float*)d_in[9];
    const float* bq2 = (const float*)d_in[10];
    float* out = (float*)d_out;

    float* ph = nullptr;
    void *pcnt = nullptr, *phb = nullptr, *pwb = nullptr;
    cudaGetSymbolAddress((void**)&ph, g_h);
    cudaGetSymbolAddress(&pcnt, g_cnt_i);
    cudaGetSymbolAddress(&phb, g_hb);
    cudaGetSymbolAddress(&pwb, g_Wb);

    const int GEMM_SMEM = (128 * 68 + 2 * 16 * 132) * 4;   // 51,712 bytes

    static cudaStream_t s2 = nullptr;
    static cudaEvent_t evA = nullptr, evW = nullptr, evB = nullptr, evC = nullptr;
    if (s2 == nullptr) {
        cudaStreamCreateWithFlags(&s2, cudaStreamNonBlocking);
        cudaEventCreateWithFlags(&evA, cudaEventDisableTiming);
        cudaEventCreateWithFlags(&evW, cudaEventDisableTiming);
        cudaEventCreateWithFlags(&evB, cudaEventDisableTiming);
        cudaEventCreateWithFlags(&evC, cudaEventDisableTiming);
        cudaFuncSetAttribute(gemm_bf16,
                             cudaFuncAttributeMaxDynamicSharedMemorySize, GEMM_SMEM);
    }

    const int NB_GEMM = (Nn + 127) / 128;
    const int NB_E    = (ETOT + 255) / 256;
    const int NB_AGG  = Nn / 8;
    const int NB_POOL = (Nn + 255) / 256;

    const u32* Wb0 = (const u32*)pwb;
    const u32* Wb1 = (const u32*)pwb + 8192;
    const u32* Ab  = (const u32*)phb;

    cudaEventRecord(evA, 0);
    cudaStreamWaitEvent(s2, evA, 0);
    cudaMemsetAsync(pcnt, 0, Nn * sizeof(int), s2);

    gemm_proj<<<NB_GEMM, 256>>>(x, Wp, bp, ph, Nn);              // kernel 1
    w_convert<<<64, 256, 0, s2>>>((const float*)d_in[11],
                                  (const float*)d_in[17]);        // kernel 2
    cudaEventRecord(evW, s2);
    hist_dst<<<NB_E, 256, 0, s2>>>(ei);                          // kernel 3

    cudaStreamWaitEvent(0, evW, 0);
    gemm_bf16<<<NB_GEMM, 256, GEMM_SMEM>>>(Ab, Wb0,
        (const float*)d_in[12], (const float*)d_in[13], Nn);     // kernel 4 (PROFILED)

    scan_dl<<<NTILE, 256, 0, s2>>>();                            // kernel 5
    csr_fill<<<NB_E, 256, 0, s2>>>(ei);                          // kernel 6
    cudaEventRecord(evB, s2);

    cudaStreamWaitEvent(0, evB, 0);
    gat_agg_ln<<<NB_AGG, 256>>>((const float*)d_in[14], (const float*)d_in[15],
                                (const float*)d_in[16], 1);

    gemm_bf16<<<NB_GEMM, 256, GEMM_SMEM>>>(Ab, Wb1,
        (const float*)d_in[18], (const float*)d_in[19], Nn);
    gat_agg_ln<<<NB_AGG, 256>>>((const float*)d_in[20], (const float*)d_in[21],
                                (const float*)d_in[22], 0);

    pool_clear<<<(Gq * Hq + 255) / 256, 256, 0, s2>>>();
    cudaEventRecord(evC, s2);
    cudaStreamWaitEvent(0, evC, 0);
    pool_chunk<<<NB_POOL, 128>>>(n2g);
    final_mlp<<<Gq, 256>>>(Wq1, bq1, gq, beq, Wq2, bq2, out);
}

// round 16
// speedup vs baseline: 1.4633x; 1.2304x over previous
#include <cuda_runtime.h>
#include <cuda_bf16.h>
#include <math.h>

#define Nn   100000
#define Ee   1600000
#define ETOT (Ee + Nn)
#define DINq 16
#define Hq   128
#define HEADSq 4
#define Gq   64
#define FOUTq 256
#define NTILE ((Nn + 255) / 256)

typedef unsigned long long u64;
typedef unsigned int u32;

// ---- scratch (static device memory) ----
__device__ float g_h[(size_t)Nn * Hq];
__device__ u32   g_hb[(size_t)Nn * (Hq / 2)];    // bf16x2 copy of h (GEMM A input)
__device__ u32   g_hpb[(size_t)Nn * (Hq / 2)];   // bf16x2 h@Wg
__device__ u32   g_Wb[2 * 8192];                 // pre-packed layer weights
__device__ float g_alS[Nn * HEADSq];
__device__ float g_alD[Nn * HEADSq];
__device__ int   g_cnt_i[Nn];
__device__ int   g_rowptr[Nn + 1];
__device__ int   g_cursor[Nn];
__device__ int   g_csr_src[ETOT];
__device__ u64   g_tstat[NTILE];
__device__ float g_psum[Gq * Hq];
__device__ float g_pmax[Gq * Hq];
__device__ float g_gcnt[Gq];

#define FLAG_AGG (1ull << 62)
#define FLAG_INC (1ull << 63)

__device__ __forceinline__ void atomicMaxFloat(float* addr, float v) {
    if (v >= 0.0f) atomicMax((int*)addr, __float_as_int(v));
    else           atomicMin((unsigned int*)addr, __float_as_uint(v));
}

__device__ __forceinline__ float gelu_exact(float v) {
    return 0.5f * v * (1.0f + erff(v * 0.70710678118654752f));
}

__device__ __forceinline__ u32 bfpack(float lo, float hi) {
    u32 r; asm("cvt.rn.bf16x2.f32 %0, %1, %2;" : "=r"(r) : "f"(hi), "f"(lo)); return r;
}

__device__ __forceinline__ void mma_bf16(float* c, const u32* a, u32 b0, u32 b1) {
    asm volatile("mma.sync.aligned.m16n8k16.row.col.f32.bf16.bf16.f32 "
        "{%0,%1,%2,%3}, {%4,%5,%6,%7}, {%8,%9}, {%0,%1,%2,%3};"
        : "+f"(c[0]), "+f"(c[1]), "+f"(c[2]), "+f"(c[3])
        : "r"(a[0]), "r"(a[1]), "r"(a[2]), "r"(a[3]), "r"(b0), "r"(b1));
}

// ---- packed f32x2 helpers ----
__device__ __forceinline__ void pfma(u64& d, u64 a, u64 b) {
    asm("fma.rn.f32x2 %0, %1, %2, %0;" : "+l"(d) : "l"(a), "l"(b));
}
__device__ __forceinline__ u64 pku(u32 lo, u32 hi) {
    u64 r; asm("mov.b64 %0, {%1,%2};" : "=l"(r) : "r"(lo), "r"(hi)); return r;
}
__device__ __forceinline__ u64 pkf(float lo, float hi) {
    u64 r; asm("mov.b64 %0, {%1,%2};" : "=l"(r) : "f"(lo), "f"(hi)); return r;
}
__device__ __forceinline__ u64 swap64(u64 p) { return pku((u32)(p >> 32), (u32)p); }
__device__ __forceinline__ float lo32(u64 p) { return __uint_as_float((u32)p); }
__device__ __forceinline__ float hi32(u64 p) { return __uint_as_float((u32)(p >> 32)); }
__device__ __forceinline__ u64 bfexpand(u32 w) {
    return pku(w << 16, w & 0xffff0000u);
}

// ------- weight pre-pack: W[k][n] fp32 -> Wu word layout [chunk][kp][n] -------
__global__ void w_convert(const float* __restrict__ W0, const float* __restrict__ W1)
{
    int i = blockIdx.x * 256 + threadIdx.x;
    if (i >= 2 * 8192) return;
    const float* W = (i < 8192) ? W0 : W1;
    int wi = i & 8191;
    int cc = wi >> 11;
    int kp = (wi >> 7) & 15;
    int n  = wi & 127;
    int k  = cc * 32 + 2 * kp;
    g_Wb[i] = bfpack(W[k * Hq + n], W[(k + 1) * Hq + n]);
}

// ------- proj GEMM (K=16): h = gelu(x @ Wp + bp), FFMA2; writes fp32 + bf16 -------
__global__ void gemm_proj(const float* __restrict__ A, const float* __restrict__ W,
                          const float* __restrict__ bias, float* __restrict__ C, int M)
{
    const int BN = 128, BK = 16;
    __shared__ float As[BK][BN + 4];
    __shared__ float Ws[BK][Hq + 4];
    int tid = threadIdx.x;
    int tx = tid & 15, ty = tid >> 4;
    int m0 = blockIdx.x * BN;
    int c0 = tx * 8;
    int r0 = ty * 8;

    u64 acc[4][4][2];
#pragma unroll
    for (int rp = 0; rp < 4; rp++)
#pragma unroll
        for (int cp = 0; cp < 4; cp++) { acc[rp][cp][0] = 0ull; acc[rp][cp][1] = 0ull; }

#pragma unroll
    for (int i = tid; i < BN * BK; i += 256) {
        int r = i >> 4, k = i & 15;
        As[k][r] = (m0 + r < M) ? A[(size_t)(m0 + r) * DINq + k] : 0.f;
    }
#pragma unroll
    for (int i = tid; i < BK * Hq; i += 256) {
        int k = i >> 7, c = i & 127;
        Ws[k][c] = W[(size_t)k * Hq + c];
    }
    __syncthreads();
#pragma unroll
    for (int kk = 0; kk < BK; kk++) {
        ulonglong2 ra = *(const ulonglong2*)&As[kk][r0];
        ulonglong2 rb = *(const ulonglong2*)&As[kk][r0 + 4];
        ulonglong2 wa = *(const ulonglong2*)&Ws[kk][c0];
        ulonglong2 wb = *(const ulonglong2*)&Ws[kk][c0 + 4];
        u64 rr[4] = {ra.x, ra.y, rb.x, rb.y};
        u64 cn[4] = {wa.x, wa.y, wb.x, wb.y};
        u64 cs[4] = {swap64(wa.x), swap64(wa.y), swap64(wb.x), swap64(wb.y)};
#pragma unroll
        for (int rp = 0; rp < 4; rp++)
#pragma unroll
            for (int cp = 0; cp < 4; cp++) {
                pfma(acc[rp][cp][0], rr[rp], cn[cp]);
                pfma(acc[rp][cp][1], rr[rp], cs[cp]);
            }
    }

    float v[8][8];
#pragma unroll
    for (int rp = 0; rp < 4; rp++)
#pragma unroll
        for (int cp = 0; cp < 4; cp++) {
            v[2 * rp][2 * cp]         = lo32(acc[rp][cp][0]);
            v[2 * rp + 1][2 * cp + 1] = hi32(acc[rp][cp][0]);
            v[2 * rp][2 * cp + 1]     = lo32(acc[rp][cp][1]);
            v[2 * rp + 1][2 * cp]     = hi32(acc[rp][cp][1]);
        }

    float b8[8];
#pragma unroll
    for (int q = 0; q < 8; q++) b8[q] = bias[c0 + q];
#pragma unroll
    for (int r = 0; r < 8; r++) {
        int m = m0 + r0 + r;
        if (m < M) {
#pragma unroll
            for (int q = 0; q < 8; q++) v[r][q] = gelu_exact(v[r][q] + b8[q]);
            float4 o0 = make_float4(v[r][0], v[r][1], v[r][2], v[r][3]);
            float4 o1 = make_float4(v[r][4], v[r][5], v[r][6], v[r][7]);
            *(float4*)&C[(size_t)m * Hq + c0] = o0;
            *(float4*)&C[(size_t)m * Hq + c0 + 4] = o1;
            uint4 ob;
            ob.x = bfpack(v[r][0], v[r][1]);
            ob.y = bfpack(v[r][2], v[r][3]);
            ob.z = bfpack(v[r][4], v[r][5]);
            ob.w = bfpack(v[r][6], v[r][7]);
            *(uint4*)&g_hb[(size_t)m * 64 + tx * 4] = ob;
        }
    }
}

// ------- layer GEMM: bf16 MMA, pre-packed operands, A resident, W double-buffered -------
__global__ void __launch_bounds__(256, 2) gemm_bf16(
    const u32* __restrict__ Ab, const u32* __restrict__ Wb,
    const float* __restrict__ a_s, const float* __restrict__ a_d, int M)
{
    extern __shared__ u32 dyn[];
    u32* Au = dyn;                    // [128][68]
    u32* Wu = dyn + 128 * 68;         // [2][16][132]
    int tid = threadIdx.x;
    int w = tid >> 5, lane = tid & 31;
    int wr = w >> 1, wc = w & 1;
    int q = lane & 3, g = lane >> 2;
    int m0 = blockIdx.x * 128;

    float c[2][8][4];
#pragma unroll
    for (int mt = 0; mt < 2; mt++)
#pragma unroll
        for (int nt = 0; nt < 8; nt++)
#pragma unroll
            for (int f = 0; f < 4; f++) c[mt][nt][f] = 0.f;

#pragma unroll
    for (int it = 0; it < 8; it++) {
        int widx4 = it * 256 + tid;
        int wd = widx4 * 4;
        int r = wd >> 6, cI = wd & 63;
        uint4 v = make_uint4(0u, 0u, 0u, 0u);
        if (m0 + r < M) v = *(const uint4*)&Ab[(size_t)(m0 + r) * 64 + cI];
        *(uint4*)&Au[r * 68 + cI] = v;
    }
    int wkp = tid >> 4, wnI = (tid * 8) & 127;
    uint4 wA = *(const uint4*)&Wb[tid * 8];
    uint4 wB = *(const uint4*)&Wb[tid * 8 + 4];
    *(uint4*)&Wu[wkp * 132 + wnI]     = wA;
    *(uint4*)&Wu[wkp * 132 + wnI + 4] = wB;
    __syncthreads();

    for (int cc = 0; cc < 4; cc++) {
        if (cc < 3) {
            wA = *(const uint4*)&Wb[(cc + 1) * 2048 + tid * 8];
            wB = *(const uint4*)&Wb[(cc + 1) * 2048 + tid * 8 + 4];
        }
        int bufo = (cc & 1) * 2112;
#pragma unroll
        for (int kh = 0; kh < 2; kh++) {
            int ks = cc * 2 + kh;
            int kpA = ks * 8 + q;
            int kpW = kh * 8 + q;
            u32 af[2][4];
#pragma unroll
            for (int mt = 0; mt < 2; mt++) {
                int r = wr * 32 + mt * 16;
                af[mt][0] = Au[(r + g) * 68 + kpA];
                af[mt][1] = Au[(r + g + 8) * 68 + kpA];
                af[mt][2] = Au[(r + g) * 68 + kpA + 4];
                af[mt][3] = Au[(r + g + 8) * 68 + kpA + 4];
            }
#pragma unroll
            for (int nt = 0; nt < 8; nt++) {
                int n = wc * 64 + nt * 8 + g;
                u32 b0 = Wu[bufo + kpW * 132 + n];
                u32 b1 = Wu[bufo + (kpW + 4) * 132 + n];
                mma_bf16(c[0][nt], af[0], b0, b1);
                mma_bf16(c[1][nt], af[1], b0, b1);
            }
        }
        if (cc < 3) {
            int b2 = ((cc + 1) & 1) * 2112;
            *(uint4*)&Wu[b2 + wkp * 132 + wnI]     = wA;
            *(uint4*)&Wu[b2 + wkp * 132 + wnI + 4] = wB;
        }
        __syncthreads();
    }

#pragma unroll
    for (int mt = 0; mt < 2; mt++)
#pragma unroll
        for (int half = 0; half < 2; half++) {
            int m = m0 + wr * 32 + mt * 16 + g + half * 8;
            if (m < M) {
#pragma unroll
                for (int nt = 0; nt < 8; nt++) {
                    u32 pw = bfpack(c[mt][nt][2 * half], c[mt][nt][2 * half + 1]);
                    g_hpb[(size_t)m * (Hq / 2) + wc * 32 + nt * 4 + q] = pw;
                }
            }
        }

    float asv[8][2], adv[8][2];
#pragma unroll
    for (int nt = 0; nt < 8; nt++) {
        int col = wc * 64 + nt * 8 + 2 * q;
        asv[nt][0] = a_s[col];     asv[nt][1] = a_s[col + 1];
        adv[nt][0] = a_d[col];     adv[nt][1] = a_d[col + 1];
    }
#pragma unroll
    for (int mt = 0; mt < 2; mt++)
#pragma unroll
        for (int half = 0; half < 2; half++) {
            int m = m0 + wr * 32 + mt * 16 + g + half * 8;
            float ps0 = 0.f, ps1 = 0.f, pd0 = 0.f, pd1 = 0.f;
#pragma unroll
            for (int nt = 0; nt < 8; nt++) {
                float x0 = c[mt][nt][2 * half], x1 = c[mt][nt][2 * half + 1];
                float s = x0 * asv[nt][0] + x1 * asv[nt][1];
                float d = x0 * adv[nt][0] + x1 * adv[nt][1];
                if (nt < 4) { ps0 += s; pd0 += d; }
                else        { ps1 += s; pd1 += d; }
            }
            ps0 += __shfl_xor_sync(0xffffffffu, ps0, 1);
            ps1 += __shfl_xor_sync(0xffffffffu, ps1, 1);
            pd0 += __shfl_xor_sync(0xffffffffu, pd0, 1);
            pd1 += __shfl_xor_sync(0xffffffffu, pd1, 1);
            ps0 += __shfl_xor_sync(0xffffffffu, ps0, 2);
            ps1 += __shfl_xor_sync(0xffffffffu, ps1, 2);
            pd0 += __shfl_xor_sync(0xffffffffu, pd0, 2);
            pd1 += __shfl_xor_sync(0xffffffffu, pd1, 2);
            if (q == 0 && m < M) {
                int hb = wc * 2;
                g_alS[m * 4 + hb]     = ps0;
                g_alS[m * 4 + hb + 1] = ps1;
                g_alD[m * 4 + hb]     = pd0;
                g_alD[m * 4 + hb + 1] = pd1;
            }
        }
}

// ================= CSR build =================
__global__ void hist_dst(const int* __restrict__ ei)
{
    int e = blockIdx.x * blockDim.x + threadIdx.x;
    if (e < NTILE) g_tstat[e] = 0;
    if (e >= ETOT) return;
    int d = (e < Ee) ? ei[Ee + e] : (e - Ee);
    atomicAdd(&g_cnt_i[d], 1);
}

__global__ void scan_dl()
{
    __shared__ int s[256];
    __shared__ int s_prefix;
    int bid = blockIdx.x, tid = threadIdx.x;
    int i = bid * 256 + tid;
    int v = (i < Nn) ? g_cnt_i[i] : 0;
    s[tid] = v;
    __syncthreads();
#pragma unroll
    for (int o = 1; o < 256; o <<= 1) {
        int t = (tid >= o) ? s[tid - o] : 0;
        __syncthreads();
        s[tid] += t;
        __syncthreads();
    }
    int incl = s[tid];
    int agg  = s[255];

    if (tid == 0) {
        u64 pub = (bid == 0) ? (FLAG_INC | (u64)(u32)agg) : (FLAG_AGG | (u64)(u32)agg);
        atomicExch((unsigned long long*)&g_tstat[bid], pub);
        if (bid == 0) s_prefix = 0;
    }

    if (bid > 0 && tid < 32) {
        int lane = tid;
        u32 running = 0;
        int look = bid - 1;
        while (true) {
            int t = look - lane;
            u64 st;
            if (t >= 0) {
                do { st = *(volatile u64*)&g_tstat[t]; } while (st == 0);
            } else {
                st = FLAG_INC;
            }
            u32 incm = __ballot_sync(0xffffffffu, (st & FLAG_INC) != 0);
            u32 val;
            if (incm) {
                int L = __ffs(incm) - 1;
                val = (lane <= L) ? (u32)st : 0;
            } else {
                val = (u32)st;
            }
#pragma unroll
            for (int o = 16; o; o >>= 1) val += __shfl_xor_sync(0xffffffffu, val, o);
            running += val;
            if (incm) break;
            look -= 32;
        }
        if (lane == 0) {
            atomicExch((unsigned long long*)&g_tstat[bid],
                       FLAG_INC | (u64)(u32)(running + (u32)agg));
            s_prefix = (int)running;
        }
    }
    __syncthreads();

    int pre = s_prefix;
    if (i < Nn) {
        int r = pre + incl - v;
        g_rowptr[i] = r;
        g_cursor[i] = r;
    }
    if (i == 0) g_rowptr[Nn] = ETOT;
}

__global__ void csr_fill(const int* __restrict__ ei)
{
    int e = blockIdx.x * blockDim.x + threadIdx.x;
    if (e >= ETOT) return;
    int s, d;
    if (e < Ee) { s = ei[e]; d = ei[Ee + e]; } else { s = d = e - Ee; }
    int pos = atomicAdd(&g_cursor[d], 1);
    g_csr_src[pos] = s;
}

// == GAT aggregation: warp per node, half-warp per edge, packed f32x2 FMA ==
__global__ void gat_agg_ln(const float* __restrict__ bg, const float* __restrict__ ga,
                           const float* __restrict__ be, int whb)
{
    int n = blockIdx.x * 8 + (threadIdx.x >> 5);
    if (n >= Nn) return;
    int lane = threadIdx.x & 31;
    int pairlane = lane >> 4;
    int sub = lane & 15;
    int head = sub >> 2;

    int start = g_rowptr[n];
    int end   = g_rowptr[n + 1];
    float adh = g_alD[n * 4 + head];

    u64 acc[4];
#pragma unroll
    for (int k = 0; k < 4; k++) acc[k] = 0ull;
    float den = 0.f;

    int i = start;
    for (; i + 4 <= end; i += 4) {
        int sA = g_csr_src[i + pairlane];
        int sB = g_csr_src[i + 2 + pairlane];
        float lA = g_alS[sA * 4 + head] + adh;
        float lB = g_alS[sB * 4 + head] + adh;
        lA = (lA > 0.f) ? lA : 0.2f * lA;
        lB = (lB > 0.f) ? lB : 0.2f * lB;
        float eA = __expf(lA);
        float eB = __expf(lB);
        uint4 pA = *(const uint4*)&g_hpb[(size_t)sA * 64 + sub * 4];
        uint4 pB = *(const uint4*)&g_hpb[(size_t)sB * 64 + sub * 4];
        den += eA + eB;
        u64 eAp = pkf(eA, eA);
        u64 eBp = pkf(eB, eB);
        pfma(acc[0], eAp, bfexpand(pA.x));
        pfma(acc[1], eAp, bfexpand(pA.y));
        pfma(acc[2], eAp, bfexpand(pA.z));
        pfma(acc[3], eAp, bfexpand(pA.w));
        pfma(acc[0], eBp, bfexpand(pB.x));
        pfma(acc[1], eBp, bfexpand(pB.y));
        pfma(acc[2], eBp, bfexpand(pB.z));
        pfma(acc[3], eBp, bfexpand(pB.w));
    }
    for (; i + 2 <= end; i += 2) {
        int sA = g_csr_src[i + pairlane];
        float lA = g_alS[sA * 4 + head] + adh;
        lA = (lA > 0.f) ? lA : 0.2f * lA;
        float eA = __expf(lA);
        uint4 pA = *(const uint4*)&g_hpb[(size_t)sA * 64 + sub * 4];
        den += eA;
        u64 eAp = pkf(eA, eA);
        pfma(acc[0], eAp, bfexpand(pA.x));
        pfma(acc[1], eAp, bfexpand(pA.y));
        pfma(acc[2], eAp, bfexpand(pA.z));
        pfma(acc[3], eAp, bfexpand(pA.w));
    }
    if (i < end) {
        int sA = g_csr_src[i];
        float lA = g_alS[sA * 4 + head] + adh;
        lA = (lA > 0.f) ? lA : 0.2f * lA;
        float eA = (pairlane == 0) ? __expf(lA) : 0.f;
        uint4 pA = *(const uint4*)&g_hpb[(size_t)sA * 64 + sub * 4];
        den += eA;
        u64 eAp = pkf(eA, eA);
        pfma(acc[0], eAp, bfexpand(pA.x));
        pfma(acc[1], eAp, bfexpand(pA.y));
        pfma(acc[2], eAp, bfexpand(pA.z));
        pfma(acc[3], eAp, bfexpand(pA.w));
    }

    float a[8];
#pragma unroll
    for (int k = 0; k < 4; k++) { a[2 * k] = lo32(acc[k]); a[2 * k + 1] = hi32(acc[k]); }

    den += __shfl_xor_sync(0xffffffffu, den, 16);
#pragma unroll
    for (int k = 0; k < 8; k++) a[k] += __shfl_xor_sync(0xffffffffu, a[k], 16);

    float dinv = 1.0f / (den + 1e-16f);

    int d0 = sub * 8;
    size_t base = (size_t)n * Hq + d0;
    float4 h0 = *(const float4*)&g_h[base];
    float4 h1 = *(const float4*)&g_h[base + 4];
    float4 b0 = *(const float4*)&bg[d0];
    float4 b1 = *(const float4*)&bg[d0 + 4];
    float v[8];
    v[0] = a[0] * dinv + b0.x + h0.x;
    v[1] = a[1] * dinv + b0.y + h0.y;
    v[2] = a[2] * dinv + b0.z + h0.z;
    v[3] = a[3] * dinv + b0.w + h0.w;
    v[4] = a[4] * dinv + b1.x + h1.x;
    v[5] = a[5] * dinv + b1.y + h1.y;
    v[6] = a[6] * dinv + b1.z + h1.z;
    v[7] = a[7] * dinv + b1.w + h1.w;

    float s = 0.f, t = 0.f;
#pragma unroll
    for (int k = 0; k < 8; k++) { s += v[k]; t += v[k] * v[k]; }
#pragma unroll
    for (int o = 8; o; o >>= 1) {
        s += __shfl_xor_sync(0xffffffffu, s, o);
        t += __shfl_xor_sync(0xffffffffu, t, o);
    }
    float mu = s * (1.0f / 128.0f);
    float var = t * (1.0f / 128.0f) - mu * mu;
    float rs = rsqrtf(var + 1e-5f);

    if (pairlane == 0) {
        float4 g0 = *(const float4*)&ga[d0];
        float4 g1 = *(const float4*)&ga[d0 + 4];
        float4 e0 = *(const float4*)&be[d0];
        float4 e1 = *(const float4*)&be[d0 + 4];
        float4 o0, o1;
        o0.x = (v[0] - mu) * rs * g0.x + e0.x;
        o0.y = (v[1] - mu) * rs * g0.y + e0.y;
        o0.z = (v[2] - mu) * rs * g0.z + e0.z;
        o0.w = (v[3] - mu) * rs * g0.w + e0.w;
        o1.x = (v[4] - mu) * rs * g1.x + e1.x;
        o1.y = (v[5] - mu) * rs * g1.y + e1.y;
        o1.z = (v[6] - mu) * rs * g1.z + e1.z;
        o1.w = (v[7] - mu) * rs * g1.w + e1.w;
        *(float4*)&g_h[base] = o0;
        *(float4*)&g_h[base + 4] = o1;
        if (whb) {
            uint4 ob;
            ob.x = bfpack(o0.x, o0.y);
            ob.y = bfpack(o0.z, o0.w);
            ob.z = bfpack(o1.x, o1.y);
            ob.w = bfpack(o1.z, o1.w);
            *(uint4*)&g_hb[(size_t)n * 64 + sub * 4] = ob;
        }
    }
}

// ---------------- pooling ----------------
__global__ void pool_clear()
{
    int idx = blockIdx.x * blockDim.x + threadIdx.x;
    if (idx < Gq * Hq) { g_psum[idx] = 0.f; g_pmax[idx] = -INFINITY; }
    if (idx < Gq) g_gcnt[idx] = 0.f;
}

// 64-node chunks, 128 threads (one per dim): 1563 blocks
__global__ void pool_chunk(const int* __restrict__ n2g)
{
    __shared__ int sg[64];
    int d  = threadIdx.x;
    int n0 = blockIdx.x * 64;
    int n1 = n0 + 64; if (n1 > Nn) n1 = Nn;
    int cn = n1 - n0;
    if (d < cn) sg[d] = n2g[n0 + d];
    __syncthreads();

    int   curg = sg[0];
    float sum = 0.f, mx = -INFINITY;
    int   cnt = 0;
    for (int j = 0; j < cn; j++) {
        int g = sg[j];
        if (g != curg) {
            atomicAdd(&g_psum[curg * Hq + d], sum);
            atomicMaxFloat(&g_pmax[curg * Hq + d], mx);
            if (d == 0) atomicAdd(&g_gcnt[curg], (float)cnt);
            sum = 0.f; mx = -INFINITY; cnt = 0; curg = g;
        }
        float v = g_h[(size_t)(n0 + j) * Hq + d];
        sum += v; mx = fmaxf(mx, v); cnt++;
    }
    atomicAdd(&g_psum[curg * Hq + d], sum);
    atomicMaxFloat(&g_pmax[curg * Hq + d], mx);
    if (d == 0) atomicAdd(&g_gcnt[curg], (float)cnt);
}

// ---------------- final MLP head (parallel stats, 2 threads/col GEMM1) ----------------
__global__ void final_mlp(const float* __restrict__ Wq1, const float* __restrict__ bq1,
                          const float* __restrict__ gq, const float* __restrict__ beq,
                          const float* __restrict__ Wq2, const float* __restrict__ bq2,
                          float* __restrict__ out)
{
    int g = blockIdx.x;
    int tid = threadIdx.x;   // 256
    __shared__ float emb[2 * Hq];
    __shared__ float pp[2][Hq];
    __shared__ float p[Hq];
    __shared__ float red[8];

    if (tid < Hq) emb[tid] = g_psum[g * Hq + tid] / fmaxf(g_gcnt[g], 1.0f);
    else          emb[tid] = g_pmax[g * Hq + (tid - Hq)];
    __syncthreads();

    // GEMM1: 2 threads per output column, each covers half of k
    int col = tid & 127, hf = tid >> 7;
    float t = 0.f;
#pragma unroll 4
    for (int k = 0; k < Hq; k++)
        t += emb[hf * Hq + k] * Wq1[(size_t)(hf * Hq + k) * Hq + col];
    pp[hf][col] = t;
    __syncthreads();

    float val = 0.f;
    if (tid < Hq) {
        val = pp[0][tid] + pp[1][tid] + bq1[tid];
        float s = val, q = val * val;
#pragma unroll
        for (int o = 16; o; o >>= 1) {
            s += __shfl_xor_sync(0xffffffffu, s, o);
            q += __shfl_xor_sync(0xffffffffu, q, o);
        }
        if ((tid & 31) == 0) { red[(tid >> 5) * 2] = s; red[(tid >> 5) * 2 + 1] = q; }
    }
    __syncthreads();
    float stot = red[0] + red[2] + red[4] + red[6];
    float qtot = red[1] + red[3] + red[5] + red[7];
    float mu = stot * (1.0f / 128.0f);
    float var = qtot * (1.0f / 128.0f) - mu * mu;
    float rs = rsqrtf(var + 1e-5f);

    if (tid < Hq) p[tid] = gelu_exact((val - mu) * rs * gq[tid] + beq[tid]);
    __syncthreads();

    float o = bq2[tid];
#pragma unroll 4
    for (int k = 0; k < Hq; k++) o += p[k] * Wq2[(size_t)k * FOUTq + tid];
    out[g * FOUTq + tid] = o;
}

// ---------------- launch ----------------
extern "C" void kernel_launch(void* const* d_in, const int* in_sizes, int n_in,
                              void* d_out, int out_size)
{
    const float* x   = (const float*)d_in[0];
    const int*   ei  = (const int*)d_in[1];
    const int*   n2g = (const int*)d_in[2];
    const float* Wp  = (const float*)d_in[3];
    const float* bp  = (const float*)d_in[4];
    const float* Wq1 = (const float*)d_in[5];
    const float* bq1 = (const float*)d_in[6];
    const float* gq  = (const float*)d_in[7];
    const float* beq = (const float*)d_in[8];
    const float* Wq2 = (const float*)d_in[9];
    const float* bq2 = (const float*)d_in[10];
    float* out = (float*)d_out;

    float* ph = nullptr;
    void *pcnt = nullptr, *phb = nullptr, *pwb = nullptr;
    cudaGetSymbolAddress((void**)&ph, g_h);
    cudaGetSymbolAddress(&pcnt, g_cnt_i);
    cudaGetSymbolAddress(&phb, g_hb);
    cudaGetSymbolAddress(&pwb, g_Wb);

    const int GEMM_SMEM = (128 * 68 + 2 * 16 * 132) * 4;   // 51,712 bytes

    static cudaStream_t s2 = nullptr;
    static cudaEvent_t evA = nullptr, evW = nullptr, evB = nullptr, evC = nullptr;
    if (s2 == nullptr) {
        cudaStreamCreateWithFlags(&s2, cudaStreamNonBlocking);
        cudaEventCreateWithFlags(&evA, cudaEventDisableTiming);
        cudaEventCreateWithFlags(&evW, cudaEventDisableTiming);
        cudaEventCreateWithFlags(&evB, cudaEventDisableTiming);
        cudaEventCreateWithFlags(&evC, cudaEventDisableTiming);
        cudaFuncSetAttribute(gemm_bf16,
                             cudaFuncAttributeMaxDynamicSharedMemorySize, GEMM_SMEM);
    }

    const int NB_GEMM = (Nn + 127) / 128;
    const int NB_E    = (ETOT + 255) / 256;
    const int NB_AGG  = Nn / 8;
    const int NB_POOL = (Nn + 63) / 64;

    const u32* Wb0 = (const u32*)pwb;
    const u32* Wb1 = (const u32*)pwb + 8192;
    const u32* Ab  = (const u32*)phb;

    cudaEventRecord(evA, 0);
    cudaStreamWaitEvent(s2, evA, 0);
    cudaMemsetAsync(pcnt, 0, Nn * sizeof(int), s2);

    gemm_proj<<<NB_GEMM, 256>>>(x, Wp, bp, ph, Nn);              // kernel 1
    w_convert<<<64, 256, 0, s2>>>((const float*)d_in[11],
                                  (const float*)d_in[17]);        // kernel 2
    cudaEventRecord(evW, s2);
    hist_dst<<<NB_E, 256, 0, s2>>>(ei);                          // kernel 3

    cudaStreamWaitEvent(0, evW, 0);
    gemm_bf16<<<NB_GEMM, 256, GEMM_SMEM>>>(Ab, Wb0,
        (const float*)d_in[12], (const float*)d_in[13], Nn);     // kernel 4 (PROFILED)

    scan_dl<<<NTILE, 256, 0, s2>>>();                            // kernel 5
    csr_fill<<<NB_E, 256, 0, s2>>>(ei);                          // kernel 6
    cudaEventRecord(evB, s2);

    cudaStreamWaitEvent(0, evB, 0);
    gat_agg_ln<<<NB_AGG, 256>>>((const float*)d_in[14], (const float*)d_in[15],
                                (const float*)d_in[16], 1);

    gemm_bf16<<<NB_GEMM, 256, GEMM_SMEM>>>(Ab, Wb1,
        (const float*)d_in[18], (const float*)d_in[19], Nn);
    gat_agg_ln<<<NB_AGG, 256>>>((const float*)d_in[20], (const float*)d_in[21],
                                (const float*)d_in[22], 0);

    pool_clear<<<(Gq * Hq + 255) / 256, 256, 0, s2>>>();
    cudaEventRecord(evC, s2);
    cudaStreamWaitEvent(0, evC, 0);
    pool_chunk<<<NB_POOL, 128>>>(n2g);
    final_mlp<<<Gq, 256>>>(Wq1, bq1, gq, beq, Wq2, bq2, out);
}

// round 17
// speedup vs baseline: 1.4673x; 1.0027x over previous
#include <cuda_runtime.h>
#include <cuda_bf16.h>
#include <math.h>

#define Nn   100000
#define Ee   1600000
#define ETOT (Ee + Nn)
#define DINq 16
#define Hq   128
#define HEADSq 4
#define Gq   64
#define FOUTq 256
#define NTILE ((Nn + 255) / 256)
#define LOG2E 1.44269504088896f

typedef unsigned long long u64;
typedef unsigned int u32;

// ---- scratch (static device memory) ----
__device__ float g_h[(size_t)Nn * Hq];
__device__ u32   g_hb[(size_t)Nn * (Hq / 2)];    // bf16x2 copy of h (GEMM A input)
__device__ u32   g_hpb[(size_t)Nn * (Hq / 2)];   // bf16x2 h@Wg
__device__ u32   g_Wb[2 * 8192];                 // pre-packed layer weights (slot layout)
__device__ float g_alS[Nn * HEADSq];             // pre-scaled by LOG2E
__device__ float g_alD[Nn * HEADSq];
__device__ int   g_cnt_i[Nn];
__device__ int   g_rowptr[Nn + 1];
__device__ int   g_cursor[Nn];
__device__ int   g_csr_src[ETOT];
__device__ u64   g_tstat[NTILE];
__device__ float g_psum[Gq * Hq];
__device__ float g_pmax[Gq * Hq];
__device__ float g_gcnt[Gq];

#define FLAG_AGG (1ull << 62)
#define FLAG_INC (1ull << 63)

__device__ __forceinline__ void atomicMaxFloat(float* addr, float v) {
    if (v >= 0.0f) atomicMax((int*)addr, __float_as_int(v));
    else           atomicMin((unsigned int*)addr, __float_as_uint(v));
}

__device__ __forceinline__ float gelu_exact(float v) {
    return 0.5f * v * (1.0f + erff(v * 0.70710678118654752f));
}

__device__ __forceinline__ u32 bfpack(float lo, float hi) {
    u32 r; asm("cvt.rn.bf16x2.f32 %0, %1, %2;" : "=r"(r) : "f"(hi), "f"(lo)); return r;
}

__device__ __forceinline__ float ex2f(float x) {
    float r; asm("ex2.approx.f32 %0, %1;" : "=f"(r) : "f"(x)); return r;
}

__device__ __forceinline__ void mma_bf16(float* c, const u32* a, u32 b0, u32 b1) {
    asm volatile("mma.sync.aligned.m16n8k16.row.col.f32.bf16.bf16.f32 "
        "{%0,%1,%2,%3}, {%4,%5,%6,%7}, {%8,%9}, {%0,%1,%2,%3};"
        : "+f"(c[0]), "+f"(c[1]), "+f"(c[2]), "+f"(c[3])
        : "r"(a[0]), "r"(a[1]), "r"(a[2]), "r"(a[3]), "r"(b0), "r"(b1));
}

// ---- packed f32x2 helpers ----
__device__ __forceinline__ void pfma(u64& d, u64 a, u64 b) {
    asm("fma.rn.f32x2 %0, %1, %2, %0;" : "+l"(d) : "l"(a), "l"(b));
}
__device__ __forceinline__ u64 pku(u32 lo, u32 hi) {
    u64 r; asm("mov.b64 %0, {%1,%2};" : "=l"(r) : "r"(lo), "r"(hi)); return r;
}
__device__ __forceinline__ u64 pkf(float lo, float hi) {
    u64 r; asm("mov.b64 %0, {%1,%2};" : "=l"(r) : "f"(lo), "f"(hi)); return r;
}
__device__ __forceinline__ u64 swap64(u64 p) { return pku((u32)(p >> 32), (u32)p); }
__device__ __forceinline__ float lo32(u64 p) { return __uint_as_float((u32)p); }
__device__ __forceinline__ float hi32(u64 p) { return __uint_as_float((u32)(p >> 32)); }
__device__ __forceinline__ u64 bfexpand(u32 w) {
    return pku(w << 16, w & 0xffff0000u);
}

// ---- weight pre-pack into slot layout: [layer][cc][kp][wc*64 + g*8 + nt] ----
__global__ void w_convert(const float* __restrict__ W0, const float* __restrict__ W1)
{
    int i = blockIdx.x * 256 + threadIdx.x;
    if (i >= 2 * 8192) return;
    const float* W = (i < 8192) ? W0 : W1;
    int wi = i & 8191;
    int cc = wi >> 11;
    int rem = wi & 2047;
    int kp = rem >> 7;
    int slot = rem & 127;
    int wc = slot >> 6, gg = (slot >> 3) & 7, nt = slot & 7;
    int n = wc * 64 + nt * 8 + gg;
    int k = cc * 32 + 2 * kp;
    g_Wb[i] = bfpack(W[k * Hq + n], W[(k + 1) * Hq + n]);
}

// ------- proj GEMM (K=16): BN=64, 4 rows/thread (occupancy), FFMA2 -------
__global__ void gemm_proj(const float* __restrict__ A, const float* __restrict__ W,
                          const float* __restrict__ bias, float* __restrict__ C, int M)
{
    const int BN = 64, BK = 16;
    __shared__ float As[BK][BN + 4];
    __shared__ float Ws[BK][Hq + 4];
    int tid = threadIdx.x;
    int tx = tid & 15, ty = tid >> 4;
    int m0 = blockIdx.x * BN;
    int c0 = tx * 8;
    int r0 = ty * 4;

    u64 acc[2][4][2];
#pragma unroll
    for (int rp = 0; rp < 2; rp++)
#pragma unroll
        for (int cp = 0; cp < 4; cp++) { acc[rp][cp][0] = 0ull; acc[rp][cp][1] = 0ull; }

#pragma unroll
    for (int i = tid; i < BN * BK; i += 256) {
        int r = i >> 4, k = i & 15;
        As[k][r] = (m0 + r < M) ? A[(size_t)(m0 + r) * DINq + k] : 0.f;
    }
#pragma unroll
    for (int i = tid; i < BK * Hq; i += 256) {
        int k = i >> 7, c = i & 127;
        Ws[k][c] = W[(size_t)k * Hq + c];
    }
    __syncthreads();
#pragma unroll
    for (int kk = 0; kk < BK; kk++) {
        ulonglong2 ra = *(const ulonglong2*)&As[kk][r0];
        ulonglong2 wa = *(const ulonglong2*)&Ws[kk][c0];
        ulonglong2 wb = *(const ulonglong2*)&Ws[kk][c0 + 4];
        u64 rr[2] = {ra.x, ra.y};
        u64 cn[4] = {wa.x, wa.y, wb.x, wb.y};
        u64 cs[4] = {swap64(wa.x), swap64(wa.y), swap64(wb.x), swap64(wb.y)};
#pragma unroll
        for (int rp = 0; rp < 2; rp++)
#pragma unroll
            for (int cp = 0; cp < 4; cp++) {
                pfma(acc[rp][cp][0], rr[rp], cn[cp]);
                pfma(acc[rp][cp][1], rr[rp], cs[cp]);
            }
    }

    float v[4][8];
#pragma unroll
    for (int rp = 0; rp < 2; rp++)
#pragma unroll
        for (int cp = 0; cp < 4; cp++) {
            v[2 * rp][2 * cp]         = lo32(acc[rp][cp][0]);
            v[2 * rp + 1][2 * cp + 1] = hi32(acc[rp][cp][0]);
            v[2 * rp][2 * cp + 1]     = lo32(acc[rp][cp][1]);
            v[2 * rp + 1][2 * cp]     = hi32(acc[rp][cp][1]);
        }

    float b8[8];
#pragma unroll
    for (int q = 0; q < 8; q++) b8[q] = bias[c0 + q];
#pragma unroll
    for (int r = 0; r < 4; r++) {
        int m = m0 + r0 + r;
        if (m < M) {
#pragma unroll
            for (int q = 0; q < 8; q++) v[r][q] = gelu_exact(v[r][q] + b8[q]);
            float4 o0 = make_float4(v[r][0], v[r][1], v[r][2], v[r][3]);
            float4 o1 = make_float4(v[r][4], v[r][5], v[r][6], v[r][7]);
            *(float4*)&C[(size_t)m * Hq + c0] = o0;
            *(float4*)&C[(size_t)m * Hq + c0 + 4] = o1;
            uint4 ob;
            ob.x = bfpack(v[r][0], v[r][1]);
            ob.y = bfpack(v[r][2], v[r][3]);
            ob.z = bfpack(v[r][4], v[r][5]);
            ob.w = bfpack(v[r][6], v[r][7]);
            *(uint4*)&g_hb[(size_t)m * 64 + tx * 4] = ob;
        }
    }
}

// ------- layer GEMM: bf16 MMA, slot-packed W (vector B loads), A resident -------
__global__ void __launch_bounds__(256, 2) gemm_bf16(
    const u32* __restrict__ Ab, const u32* __restrict__ Wb,
    const float* __restrict__ a_s, const float* __restrict__ a_d, int M)
{
    extern __shared__ u32 dyn[];
    u32* Au = dyn;                    // [128][68]
    u32* Wu = dyn + 128 * 68;         // [2][16][132] (slot layout)
    int tid = threadIdx.x;
    int w = tid >> 5, lane = tid & 31;
    int wr = w >> 1, wc = w & 1;
    int q = lane & 3, g = lane >> 2;
    int m0 = blockIdx.x * 128;

    float c[2][8][4];
#pragma unroll
    for (int mt = 0; mt < 2; mt++)
#pragma unroll
        for (int nt = 0; nt < 8; nt++)
#pragma unroll
            for (int f = 0; f < 4; f++) c[mt][nt][f] = 0.f;

#pragma unroll
    for (int it = 0; it < 8; it++) {
        int widx4 = it * 256 + tid;
        int wd = widx4 * 4;
        int r = wd >> 6, cI = wd & 63;
        uint4 v = make_uint4(0u, 0u, 0u, 0u);
        if (m0 + r < M) v = *(const uint4*)&Ab[(size_t)(m0 + r) * 64 + cI];
        *(uint4*)&Au[r * 68 + cI] = v;
    }
    int wkp = tid >> 4, wnI = (tid * 8) & 127;
    uint4 wA = *(const uint4*)&Wb[tid * 8];
    uint4 wB = *(const uint4*)&Wb[tid * 8 + 4];
    *(uint4*)&Wu[wkp * 132 + wnI]     = wA;
    *(uint4*)&Wu[wkp * 132 + wnI + 4] = wB;
    __syncthreads();

    int bslot = wc * 64 + g * 8;
    for (int cc = 0; cc < 4; cc++) {
        if (cc < 3) {
            wA = *(const uint4*)&Wb[(cc + 1) * 2048 + tid * 8];
            wB = *(const uint4*)&Wb[(cc + 1) * 2048 + tid * 8 + 4];
        }
        int bufo = (cc & 1) * 2112;
#pragma unroll
        for (int kh = 0; kh < 2; kh++) {
            int ks = cc * 2 + kh;
            int kpA = ks * 8 + q;
            int kpW = kh * 8 + q;
            u32 af[2][4];
#pragma unroll
            for (int mt = 0; mt < 2; mt++) {
                int r = wr * 32 + mt * 16;
                af[mt][0] = Au[(r + g) * 68 + kpA];
                af[mt][1] = Au[(r + g + 8) * 68 + kpA];
                af[mt][2] = Au[(r + g) * 68 + kpA + 4];
                af[mt][3] = Au[(r + g + 8) * 68 + kpA + 4];
            }
            uint4 B0a = *(const uint4*)&Wu[bufo + kpW * 132 + bslot];
            uint4 B0b = *(const uint4*)&Wu[bufo + kpW * 132 + bslot + 4];
            uint4 B1a = *(const uint4*)&Wu[bufo + (kpW + 4) * 132 + bslot];
            uint4 B1b = *(const uint4*)&Wu[bufo + (kpW + 4) * 132 + bslot + 4];
            u32 b0r[8] = {B0a.x, B0a.y, B0a.z, B0a.w, B0b.x, B0b.y, B0b.z, B0b.w};
            u32 b1r[8] = {B1a.x, B1a.y, B1a.z, B1a.w, B1b.x, B1b.y, B1b.z, B1b.w};
#pragma unroll
            for (int nt = 0; nt < 8; nt++) {
                mma_bf16(c[0][nt], af[0], b0r[nt], b1r[nt]);
                mma_bf16(c[1][nt], af[1], b0r[nt], b1r[nt]);
            }
        }
        if (cc < 3) {
            int b2 = ((cc + 1) & 1) * 2112;
            *(uint4*)&Wu[b2 + wkp * 132 + wnI]     = wA;
            *(uint4*)&Wu[b2 + wkp * 132 + wnI + 4] = wB;
        }
        __syncthreads();
    }

    // epilogue 1: bf16 pack of hp
#pragma unroll
    for (int mt = 0; mt < 2; mt++)
#pragma unroll
        for (int half = 0; half < 2; half++) {
            int m = m0 + wr * 32 + mt * 16 + g + half * 8;
            if (m < M) {
#pragma unroll
                for (int nt = 0; nt < 8; nt++) {
                    u32 pw = bfpack(c[mt][nt][2 * half], c[mt][nt][2 * half + 1]);
                    g_hpb[(size_t)m * (Hq / 2) + wc * 32 + nt * 4 + q] = pw;
                }
            }
        }

    // epilogue 2: attn logits (pre-scaled by LOG2E for ex2 in agg)
    float asv[8][2], adv[8][2];
#pragma unroll
    for (int nt = 0; nt < 8; nt++) {
        int col = wc * 64 + nt * 8 + 2 * q;
        asv[nt][0] = a_s[col];     asv[nt][1] = a_s[col + 1];
        adv[nt][0] = a_d[col];     adv[nt][1] = a_d[col + 1];
    }
#pragma unroll
    for (int mt = 0; mt < 2; mt++)
#pragma unroll
        for (int half = 0; half < 2; half++) {
            int m = m0 + wr * 32 + mt * 16 + g + half * 8;
            float ps0 = 0.f, ps1 = 0.f, pd0 = 0.f, pd1 = 0.f;
#pragma unroll
            for (int nt = 0; nt < 8; nt++) {
                float x0 = c[mt][nt][2 * half], x1 = c[mt][nt][2 * half + 1];
                float s = x0 * asv[nt][0] + x1 * asv[nt][1];
                float d = x0 * adv[nt][0] + x1 * adv[nt][1];
                if (nt < 4) { ps0 += s; pd0 += d; }
                else        { ps1 += s; pd1 += d; }
            }
            ps0 += __shfl_xor_sync(0xffffffffu, ps0, 1);
            ps1 += __shfl_xor_sync(0xffffffffu, ps1, 1);
            pd0 += __shfl_xor_sync(0xffffffffu, pd0, 1);
            pd1 += __shfl_xor_sync(0xffffffffu, pd1, 1);
            ps0 += __shfl_xor_sync(0xffffffffu, ps0, 2);
            ps1 += __shfl_xor_sync(0xffffffffu, ps1, 2);
            pd0 += __shfl_xor_sync(0xffffffffu, pd0, 2);
            pd1 += __shfl_xor_sync(0xffffffffu, pd1, 2);
            if (q == 0 && m < M) {
                int hb = wc * 2;
                g_alS[m * 4 + hb]     = ps0 * LOG2E;
                g_alS[m * 4 + hb + 1] = ps1 * LOG2E;
                g_alD[m * 4 + hb]     = pd0 * LOG2E;
                g_alD[m * 4 + hb + 1] = pd1 * LOG2E;
            }
        }
}

// ================= CSR build =================
__global__ void hist_dst(const int* __restrict__ ei)
{
    int e = blockIdx.x * blockDim.x + threadIdx.x;
    if (e < NTILE) g_tstat[e] = 0;
    if (e >= ETOT) return;
    int d = (e < Ee) ? ei[Ee + e] : (e - Ee);
    atomicAdd(&g_cnt_i[d], 1);
}

__global__ void scan_dl()
{
    __shared__ int s[256];
    __shared__ int s_prefix;
    int bid = blockIdx.x, tid = threadIdx.x;
    int i = bid * 256 + tid;
    int v = (i < Nn) ? g_cnt_i[i] : 0;
    s[tid] = v;
    __syncthreads();
#pragma unroll
    for (int o = 1; o < 256; o <<= 1) {
        int t = (tid >= o) ? s[tid - o] : 0;
        __syncthreads();
        s[tid] += t;
        __syncthreads();
    }
    int incl = s[tid];
    int agg  = s[255];

    if (tid == 0) {
        u64 pub = (bid == 0) ? (FLAG_INC | (u64)(u32)agg) : (FLAG_AGG | (u64)(u32)agg);
        atomicExch((unsigned long long*)&g_tstat[bid], pub);
        if (bid == 0) s_prefix = 0;
    }

    if (bid > 0 && tid < 32) {
        int lane = tid;
        u32 running = 0;
        int look = bid - 1;
        while (true) {
            int t = look - lane;
            u64 st;
            if (t >= 0) {
                do { st = *(volatile u64*)&g_tstat[t]; } while (st == 0);
            } else {
                st = FLAG_INC;
            }
            u32 incm = __ballot_sync(0xffffffffu, (st & FLAG_INC) != 0);
            u32 val;
            if (incm) {
                int L = __ffs(incm) - 1;
                val = (lane <= L) ? (u32)st : 0;
            } else {
                val = (u32)st;
            }
#pragma unroll
            for (int o = 16; o; o >>= 1) val += __shfl_xor_sync(0xffffffffu, val, o);
            running += val;
            if (incm) break;
            look -= 32;
        }
        if (lane == 0) {
            atomicExch((unsigned long long*)&g_tstat[bid],
                       FLAG_INC | (u64)(u32)(running + (u32)agg));
            s_prefix = (int)running;
        }
    }
    __syncthreads();

    int pre = s_prefix;
    if (i < Nn) {
        int r = pre + incl - v;
        g_rowptr[i] = r;
        g_cursor[i] = r;
    }
    if (i == 0) g_rowptr[Nn] = ETOT;
}

__global__ void csr_fill(const int* __restrict__ ei)
{
    int e = blockIdx.x * blockDim.x + threadIdx.x;
    if (e >= ETOT) return;
    int s, d;
    if (e < Ee) { s = ei[e]; d = ei[Ee + e]; } else { s = d = e - Ee; }
    int pos = atomicAdd(&g_cursor[d], 1);
    g_csr_src[pos] = s;
}

// == GAT aggregation: warp per node, half-warp per edge, packed f32x2 FMA, ex2 ==
__global__ void gat_agg_ln(const float* __restrict__ bg, const float* __restrict__ ga,
                           const float* __restrict__ be, int whb)
{
    int n = blockIdx.x * 8 + (threadIdx.x >> 5);
    if (n >= Nn) return;
    int lane = threadIdx.x & 31;
    int pairlane = lane >> 4;
    int sub = lane & 15;
    int head = sub >> 2;

    int start = g_rowptr[n];
    int end   = g_rowptr[n + 1];
    float adh = g_alD[n * 4 + head];

    u64 acc[4];
#pragma unroll
    for (int k = 0; k < 4; k++) acc[k] = 0ull;
    float den = 0.f;

    int i = start;
    for (; i + 4 <= end; i += 4) {
        int sA = g_csr_src[i + pairlane];
        int sB = g_csr_src[i + 2 + pairlane];
        float lA = g_alS[sA * 4 + head] + adh;
        float lB = g_alS[sB * 4 + head] + adh;
        lA = fmaxf(lA, 0.2f * lA);
        lB = fmaxf(lB, 0.2f * lB);
        float eA = ex2f(lA);
        float eB = ex2f(lB);
        uint4 pA = *(const uint4*)&g_hpb[(size_t)sA * 64 + sub * 4];
        uint4 pB = *(const uint4*)&g_hpb[(size_t)sB * 64 + sub * 4];
        den += eA + eB;
        u64 eAp = pkf(eA, eA);
        u64 eBp = pkf(eB, eB);
        pfma(acc[0], eAp, bfexpand(pA.x));
        pfma(acc[1], eAp, bfexpand(pA.y));
        pfma(acc[2], eAp, bfexpand(pA.z));
        pfma(acc[3], eAp, bfexpand(pA.w));
        pfma(acc[0], eBp, bfexpand(pB.x));
        pfma(acc[1], eBp, bfexpand(pB.y));
        pfma(acc[2], eBp, bfexpand(pB.z));
        pfma(acc[3], eBp, bfexpand(pB.w));
    }
    for (; i + 2 <= end; i += 2) {
        int sA = g_csr_src[i + pairlane];
        float lA = g_alS[sA * 4 + head] + adh;
        lA = fmaxf(lA, 0.2f * lA);
        float eA = ex2f(lA);
        uint4 pA = *(const uint4*)&g_hpb[(size_t)sA * 64 + sub * 4];
        den += eA;
        u64 eAp = pkf(eA, eA);
        pfma(acc[0], eAp, bfexpand(pA.x));
        pfma(acc[1], eAp, bfexpand(pA.y));
        pfma(acc[2], eAp, bfexpand(pA.z));
        pfma(acc[3], eAp, bfexpand(pA.w));
    }
    if (i < end) {
        int sA = g_csr_src[i];
        float lA = g_alS[sA * 4 + head] + adh;
        lA = fmaxf(lA, 0.2f * lA);
        float eA = (pairlane == 0) ? ex2f(lA) : 0.f;
        uint4 pA = *(const uint4*)&g_hpb[(size_t)sA * 64 + sub * 4];
        den += eA;
        u64 eAp = pkf(eA, eA);
        pfma(acc[0], eAp, bfexpand(pA.x));
        pfma(acc[1], eAp, bfexpand(pA.y));
        pfma(acc[2], eAp, bfexpand(pA.z));
        pfma(acc[3], eAp, bfexpand(pA.w));
    }

    float a[8];
#pragma unroll
    for (int k = 0; k < 4; k++) { a[2 * k] = lo32(acc[k]); a[2 * k + 1] = hi32(acc[k]); }

    den += __shfl_xor_sync(0xffffffffu, den, 16);
#pragma unroll
    for (int k = 0; k < 8; k++) a[k] += __shfl_xor_sync(0xffffffffu, a[k], 16);

    float dinv = 1.0f / (den + 1e-16f);

    int d0 = sub * 8;
    size_t base = (size_t)n * Hq + d0;
    float4 h0 = *(const float4*)&g_h[base];
    float4 h1 = *(const float4*)&g_h[base + 4];
    float4 b0 = *(const float4*)&bg[d0];
    float4 b1 = *(const float4*)&bg[d0 + 4];
    float v[8];
    v[0] = a[0] * dinv + b0.x + h0.x;
    v[1] = a[1] * dinv + b0.y + h0.y;
    v[2] = a[2] * dinv + b0.z + h0.z;
    v[3] = a[3] * dinv + b0.w + h0.w;
    v[4] = a[4] * dinv + b1.x + h1.x;
    v[5] = a[5] * dinv + b1.y + h1.y;
    v[6] = a[6] * dinv + b1.z + h1.z;
    v[7] = a[7] * dinv + b1.w + h1.w;

    float s = 0.f, t = 0.f;
#pragma unroll
    for (int k = 0; k < 8; k++) { s += v[k]; t += v[k] * v[k]; }
#pragma unroll
    for (int o = 8; o; o >>= 1) {
        s += __shfl_xor_sync(0xffffffffu, s, o);
        t += __shfl_xor_sync(0xffffffffu, t, o);
    }
    float mu = s * (1.0f / 128.0f);
    float var = t * (1.0f / 128.0f) - mu * mu;
    float rs = rsqrtf(var + 1e-5f);

    if (pairlane == 0) {
        float4 g0 = *(const float4*)&ga[d0];
        float4 g1 = *(const float4*)&ga[d0 + 4];
        float4 e0 = *(const float4*)&be[d0];
        float4 e1 = *(const float4*)&be[d0 + 4];
        float4 o0, o1;
        o0.x = (v[0] - mu) * rs * g0.x + e0.x;
        o0.y = (v[1] - mu) * rs * g0.y + e0.y;
        o0.z = (v[2] - mu) * rs * g0.z + e0.z;
        o0.w = (v[3] - mu) * rs * g0.w + e0.w;
        o1.x = (v[4] - mu) * rs * g1.x + e1.x;
        o1.y = (v[5] - mu) * rs * g1.y + e1.y;
        o1.z = (v[6] - mu) * rs * g1.z + e1.z;
        o1.w = (v[7] - mu) * rs * g1.w + e1.w;
        *(float4*)&g_h[base] = o0;
        *(float4*)&g_h[base + 4] = o1;
        if (whb) {
            uint4 ob;
            ob.x = bfpack(o0.x, o0.y);
            ob.y = bfpack(o0.z, o0.w);
            ob.z = bfpack(o1.x, o1.y);
            ob.w = bfpack(o1.z, o1.w);
            *(uint4*)&g_hb[(size_t)n * 64 + sub * 4] = ob;
        }
    }
}

// ---------------- pooling ----------------
__global__ void pool_clear()
{
    int idx = blockIdx.x * blockDim.x + threadIdx.x;
    if (idx < Gq * Hq) { g_psum[idx] = 0.f; g_pmax[idx] = -INFINITY; }
    if (idx < Gq) g_gcnt[idx] = 0.f;
}

__global__ void pool_chunk(const int* __restrict__ n2g)
{
    __shared__ int sg[64];
    int d  = threadIdx.x;
    int n0 = blockIdx.x * 64;
    int n1 = n0 + 64; if (n1 > Nn) n1 = Nn;
    int cn = n1 - n0;
    if (d < cn) sg[d] = n2g[n0 + d];
    __syncthreads();

    int   curg = sg[0];
    float sum = 0.f, mx = -INFINITY;
    int   cnt = 0;
    for (int j = 0; j < cn; j++) {
        int g = sg[j];
        if (g != curg) {
            atomicAdd(&g_psum[curg * Hq + d], sum);
            atomicMaxFloat(&g_pmax[curg * Hq + d], mx);
            if (d == 0) atomicAdd(&g_gcnt[curg], (float)cnt);
            sum = 0.f; mx = -INFINITY; cnt = 0; curg = g;
        }
        float v = g_h[(size_t)(n0 + j) * Hq + d];
        sum += v; mx = fmaxf(mx, v); cnt++;
    }
    atomicAdd(&g_psum[curg * Hq + d], sum);
    atomicMaxFloat(&g_pmax[curg * Hq + d], mx);
    if (d == 0) atomicAdd(&g_gcnt[curg], (float)cnt);
}

// ---------------- final MLP head (parallel stats, 2 threads/col GEMM1) ----------------
__global__ void final_mlp(const float* __restrict__ Wq1, const float* __restrict__ bq1,
                          const float* __restrict__ gq, const float* __restrict__ beq,
                          const float* __restrict__ Wq2, const float* __restrict__ bq2,
                          float* __restrict__ out)
{
    int g = blockIdx.x;
    int tid = threadIdx.x;   // 256
    __shared__ float emb[2 * Hq];
    __shared__ float pp[2][Hq];
    __shared__ float p[Hq];
    __shared__ float red[8];

    if (tid < Hq) emb[tid] = g_psum[g * Hq + tid] / fmaxf(g_gcnt[g], 1.0f);
    else          emb[tid] = g_pmax[g * Hq + (tid - Hq)];
    __syncthreads();

    int col = tid & 127, hf = tid >> 7;
    float t = 0.f;
#pragma unroll 4
    for (int k = 0; k < Hq; k++)
        t += emb[hf * Hq + k] * Wq1[(size_t)(hf * Hq + k) * Hq + col];
    pp[hf][col] = t;
    __syncthreads();

    float val = 0.f;
    if (tid < Hq) {
        val = pp[0][tid] + pp[1][tid] + bq1[tid];
        float s = val, q = val * val;
#pragma unroll
        for (int o = 16; o; o >>= 1) {
            s += __shfl_xor_sync(0xffffffffu, s, o);
            q += __shfl_xor_sync(0xffffffffu, q, o);
        }
        if ((tid & 31) == 0) { red[(tid >> 5) * 2] = s; red[(tid >> 5) * 2 + 1] = q; }
    }
    __syncthreads();
    float stot = red[0] + red[2] + red[4] + red[6];
    float qtot = red[1] + red[3] + red[5] + red[7];
    float mu = stot * (1.0f / 128.0f);
    float var = qtot * (1.0f / 128.0f) - mu * mu;
    float rs = rsqrtf(var + 1e-5f);

    if (tid < Hq) p[tid] = gelu_exact((val - mu) * rs * gq[tid] + beq[tid]);
    __syncthreads();

    float o = bq2[tid];
#pragma unroll 4
    for (int k = 0; k < Hq; k++) o += p[k] * Wq2[(size_t)k * FOUTq + tid];
    out[g * FOUTq + tid] = o;
}

// ---------------- launch ----------------
extern "C" void kernel_launch(void* const* d_in, const int* in_sizes, int n_in,
                              void* d_out, int out_size)
{
    const float* x   = (const float*)d_in[0];
    const int*   ei  = (const int*)d_in[1];
    const int*   n2g = (const int*)d_in[2];
    const float* Wp  = (const float*)d_in[3];
    const float* bp  = (const float*)d_in[4];
    const float* Wq1 = (const float*)d_in[5];
    const float* bq1 = (const float*)d_in[6];
    const float* gq  = (const float*)d_in[7];
    const float* beq = (const float*)d_in[8];
    const float* Wq2 = (const float*)d_in[9];
    const float* bq2 = (const float*)d_in[10];
    float* out = (float*)d_out;

    float* ph = nullptr;
    void *pcnt = nullptr, *phb = nullptr, *pwb = nullptr;
    cudaGetSymbolAddress((void**)&ph, g_h);
    cudaGetSymbolAddress(&pcnt, g_cnt_i);
    cudaGetSymbolAddress(&phb, g_hb);
    cudaGetSymbolAddress(&pwb, g_Wb);

    const int GEMM_SMEM = (128 * 68 + 2 * 16 * 132) * 4;   // 51,712 bytes

    static cudaStream_t s2 = nullptr;
    static cudaEvent_t evA = nullptr, evW = nullptr, evB = nullptr, evC = nullptr;
    if (s2 == nullptr) {
        cudaStreamCreateWithFlags(&s2, cudaStreamNonBlocking);
        cudaEventCreateWithFlags(&evA, cudaEventDisableTiming);
        cudaEventCreateWithFlags(&evW, cudaEventDisableTiming);
        cudaEventCreateWithFlags(&evB, cudaEventDisableTiming);
        cudaEventCreateWithFlags(&evC, cudaEventDisableTiming);
        cudaFuncSetAttribute(gemm_bf16,
                             cudaFuncAttributeMaxDynamicSharedMemorySize, GEMM_SMEM);
    }

    const int NB_PROJ = (Nn + 63) / 64;
    const int NB_GEMM = (Nn + 127) / 128;
    const int NB_E    = (ETOT + 255) / 256;
    const int NB_AGG  = Nn / 8;
    const int NB_POOL = (Nn + 63) / 64;

    const u32* Wb0 = (const u32*)pwb;
    const u32* Wb1 = (const u32*)pwb + 8192;
    const u32* Ab  = (const u32*)phb;

    cudaEventRecord(evA, 0);
    cudaStreamWaitEvent(s2, evA, 0);
    cudaMemsetAsync(pcnt, 0, Nn * sizeof(int), s2);

    gemm_proj<<<NB_PROJ, 256>>>(x, Wp, bp, ph, Nn);              // kernel 1
    w_convert<<<64, 256, 0, s2>>>((const float*)d_in[11],
                                  (const float*)d_in[17]);        // kernel 2
    cudaEventRecord(evW, s2);
    hist_dst<<<NB_E, 256, 0, s2>>>(ei);                          // kernel 3

    cudaStreamWaitEvent(0, evW, 0);
    gemm_bf16<<<NB_GEMM, 256, GEMM_SMEM>>>(Ab, Wb0,
        (const float*)d_in[12], (const float*)d_in[13], Nn);     // kernel 4 (PROFILED)

    scan_dl<<<NTILE, 256, 0, s2>>>();                            // kernel 5
    csr_fill<<<NB_E, 256, 0, s2>>>(ei);                          // kernel 6
    cudaEventRecord(evB, s2);

    cudaStreamWaitEvent(0, evB, 0);
    gat_agg_ln<<<NB_AGG, 256>>>((const float*)d_in[14], (const float*)d_in[15],
                                (const float*)d_in[16], 1);

    gemm_bf16<<<NB_GEMM, 256, GEMM_SMEM>>>(Ab, Wb1,
        (const float*)d_in[18], (const float*)d_in[19], Nn);
    gat_agg_ln<<<NB_AGG, 256>>>((const float*)d_in[20], (const float*)d_in[21],
                                (const float*)d_in[22], 0);

    pool_clear<<<(Gq * Hq + 255) / 256, 256, 0, s2>>>();
    cudaEventRecord(evC, s2);
    cudaStreamWaitEvent(0, evC, 0);
    pool_chunk<<<NB_POOL, 128>>>(n2g);
    final_mlp<<<Gq, 256>>>(Wq1, bq1, gq, beq, Wq2, bq2, out);
}